// round 12
// baseline (speedup 1.0000x reference)
#include <cuda_runtime.h>
#include <cuda_bf16.h>
#include <cstdint>
#include <math.h>

// Problem constants
#define Hd   128
#define Bg   512
#define Nn   8192
#define Ee   16384
#define EDIM 32

// ---------------- scratch (device globals; no allocation) ----------------
__device__ float g_transform[268435456];   // [E, H*H] = 1 GiB
__device__ __nv_bfloat16 g_hmid_hi[Ee * Hd];
__device__ __nv_bfloat16 g_hmid_lo[Ee * Hd];
__device__ __nv_bfloat16 g_w2T_hi[16384 * 128];   // [N, K] = W2 transposed
__device__ __nv_bfloat16 g_w2T_lo[16384 * 128];
__device__ float g_h[Nn * Hd];             // layer_input / hx  [N, 128]
__device__ float g_upd[Nn * Hd];           // scatter target     [N, 128]
__device__ float g_wihT[Hd * 384];         // gru w_ih transposed [j][t]
__device__ float g_whhT[Hd * 384];
__device__ float g_lihT[256 * 512];        // lstm w_ih transposed [j][t]
__device__ float g_lhhT[Hd * 512];
__device__ float g_hs[Bg * Hd];            // set2set h
__device__ float g_cs[Bg * Hd];            // set2set c
__device__ float g_qs[Bg * 256];           // q_star

__device__ __forceinline__ float sigm(float x) { return 1.0f / (1.0f + expf(-x)); }

__device__ __forceinline__ uint32_t smem_u32(const void* p) {
    uint32_t a;
    asm("{ .reg .u64 t; cvta.to.shared.u64 t, %1; cvt.u32.u64 %0, t; }" : "=r"(a) : "l"(p));
    return a;
}

#define LDSM_X4(r, a) \
    asm volatile("ldmatrix.sync.aligned.m8n8.x4.shared.b16 {%0,%1,%2,%3}, [%4];" \
        : "=r"((r)[0]), "=r"((r)[1]), "=r"((r)[2]), "=r"((r)[3]) : "r"(a))

__device__ __forceinline__ void mma16816(float* c, const uint32_t* a, uint32_t b0, uint32_t b1) {
    asm volatile("mma.sync.aligned.m16n8k16.row.col.f32.bf16.bf16.f32 "
        "{%0,%1,%2,%3}, {%4,%5,%6,%7}, {%8,%9}, {%0,%1,%2,%3};"
        : "+f"(c[0]), "+f"(c[1]), "+f"(c[2]), "+f"(c[3])
        : "r"(a[0]), "r"(a[1]), "r"(a[2]), "r"(a[3]), "r"(b0), "r"(b1));
}

#define CP_ASYNC16(dst, src) \
    asm volatile("cp.async.cg.shared.global [%0], [%1], 16;" :: "r"(dst), "l"(src) : "memory")
#define CP_COMMIT() asm volatile("cp.async.commit_group;" ::: "memory")
#define CP_WAIT(n)  asm volatile("cp.async.wait_group %0;" :: "n"(n) : "memory")

// ---------------- init: node embedding gather ----------------
__global__ void k_init_h(const int* __restrict__ ut, const float* __restrict__ emb) {
    int n = blockIdx.x, t = threadIdx.x;
    g_h[n * Hd + t] = emb[ut[n] * Hd + t];
}

// ---------------- prep: W2 transpose/split + weight transposes + zeroing -----
__global__ void __launch_bounds__(256) k_prep(const float* __restrict__ w2,
        const float* __restrict__ gih, const float* __restrict__ ghh,
        const float* __restrict__ lih, const float* __restrict__ lhh) {
    int bid = blockIdx.x, tid = threadIdx.x;
    if (bid < 2048) {
        __shared__ float ts[32][33];
        int kt = (bid & 3) * 32, nt = (bid >> 2) * 32;
        int r = tid >> 3, c4 = (tid & 7) * 4;
        const float4 v = *(const float4*)&w2[(size_t)(kt + r) * 16384 + nt + c4];
        ts[r][c4] = v.x; ts[r][c4 + 1] = v.y; ts[r][c4 + 2] = v.z; ts[r][c4 + 3] = v.w;
        __syncthreads();
        int n = nt + r;
        __nv_bfloat16 hi[4], lo[4];
#pragma unroll
        for (int q = 0; q < 4; q++) {
            float val = ts[c4 + q][r];
            hi[q] = __float2bfloat16(val);
            lo[q] = __float2bfloat16(val - __bfloat162float(hi[q]));
        }
        *(uint2*)&g_w2T_hi[(size_t)n * 128 + kt + c4] = *(uint2*)hi;
        *(uint2*)&g_w2T_lo[(size_t)n * 128 + kt + c4] = *(uint2*)lo;
        return;
    }
    long i = (long)(bid - 2048) * 256 + tid;
    if (i < 49152) { int t = i / 128, j = i % 128; g_wihT[j * 384 + t] = gih[i]; g_whhT[j * 384 + t] = ghh[i]; return; }
    i -= 49152;
    if (i < 131072) { int t = i / 256, j = i % 256; g_lihT[j * 512 + t] = lih[i]; return; }
    i -= 131072;
    if (i < 65536) { int t = i / 128, j = i % 128; g_lhhT[j * 512 + t] = lhh[i]; return; }
    i -= 65536;
    if (i < Nn * Hd) { g_upd[i] = 0.0f; return; }
    i -= Nn * Hd;
    if (i < Bg * Hd) { g_hs[i] = 0.0f; return; }
    i -= Bg * Hd;
    if (i < Bg * Hd) { g_cs[i] = 0.0f; return; }
    i -= Bg * Hd;
    if (i < Bg * 256) { g_qs[i] = 0.0f; return; }
}

// ---------------- edge hidden: hmid = relu(ef @ W1 + b1), split to bf16 hi/lo
__global__ void k_edge_hidden(const float* __restrict__ ef, const float* __restrict__ w1,
                              const float* __restrict__ b1) {
    int e = blockIdx.x, t = threadIdx.x;
    __shared__ float efs[EDIM];
    if (t < EDIM) efs[t] = ef[e * EDIM + t];
    __syncthreads();
    float acc = b1[t];
#pragma unroll
    for (int k = 0; k < EDIM; k++) acc += efs[k] * w1[k * Hd + t];
    acc = fmaxf(acc, 0.0f);
    __nv_bfloat16 hi = __float2bfloat16(acc);
    float r = acc - __bfloat162float(hi);
    g_hmid_hi[e * Hd + t] = hi;
    g_hmid_lo[e * Hd + t] = __float2bfloat16(r);
}

// ---------------- cp.async-pipelined mma.sync GEMM + fused layer-1 message --
#define STAGE 98304
#define SB_AL 16384
#define SB_BH 32768
#define SB_BL 65536
#define OFF_MSG 196608
#define OFF_IDX 197632
#define SMEM_GEMM 198144
__global__ void __launch_bounds__(512, 1) k_gemm_mma(const float* __restrict__ bias,
        const int* __restrict__ node_in, const int* __restrict__ node_out) {
    extern __shared__ char sm[];
    const int tid = threadIdx.x;
    const int wid = tid >> 5, l = tid & 31;
    const int wm = wid & 3, wn = wid >> 2;            // 4 x 4 warp grid
    const int rowBase = blockIdx.y * 128;
    const int colBase = blockIdx.x * 256;
    const uint32_t smB = smem_u32(sm);
    int* idx = (int*)(sm + OFF_IDX);

    // issue both K-chunk stages
#pragma unroll
    for (int s = 0; s < 2; s++) {
        const uint32_t sb = smB + s * STAGE;
        const int kOff = s * 64;
#pragma unroll
        for (int i0 = 0; i0 < 1024; i0 += 512) {
            int i = i0 + tid;
            int r = i >> 3, kk = i & 7;
            uint32_t off = ((uint32_t)r << 7) + ((uint32_t)kk << 4);
            off ^= (r & 7) << 4;
            const size_t gi = (size_t)(rowBase + r) * 128 + kOff + kk * 8;
            CP_ASYNC16(sb + off, &g_hmid_hi[gi]);
            CP_ASYNC16(sb + SB_AL + off, &g_hmid_lo[gi]);
        }
#pragma unroll
        for (int i0 = 0; i0 < 2048; i0 += 512) {
            int i = i0 + tid;
            int r = i >> 3, kk = i & 7;
            uint32_t off = ((uint32_t)r << 7) + ((uint32_t)kk << 4);
            off ^= (r & 7) << 4;
            const size_t gi = (size_t)(colBase + r) * 128 + kOff + kk * 8;
            CP_ASYNC16(sb + SB_BH + off, &g_w2T_hi[gi]);
            CP_ASYNC16(sb + SB_BL + off, &g_w2T_lo[gi]);
        }
        CP_COMMIT();
    }
    if (tid < 128) idx[tid] = node_in[rowBase + tid];
    if (tid >= 256 && tid < 512) ((float*)(sm + OFF_MSG))[tid - 256] = 0.0f;

    float acc[2][8][4];
#pragma unroll
    for (int mf = 0; mf < 2; mf++)
#pragma unroll
        for (int nf = 0; nf < 8; nf++)
#pragma unroll
            for (int q = 0; q < 4; q++) acc[mf][nf][q] = 0.0f;

    const int rA = l & 15;
    const int ksA = (l >> 4) & 1;
    const int nAdd = (l & 7) + ((l >> 4) << 3);
    const int kAdd = ((l >> 3) & 1) << 3;

    // MMA issue is product-major within each q so that same-accumulator RAW
    // chains are spaced 4 instructions apart (was 2).
#define DO_CHUNK(SB)                                                              \
    _Pragma("unroll")                                                             \
    for (int ks = 0; ks < 4; ks++) {                                              \
        const int k0 = ks * 16;                                                   \
        uint32_t rah[2][4], ral[2][4];                                            \
        _Pragma("unroll")                                                         \
        for (int mf = 0; mf < 2; mf++) {                                          \
            int r = wm * 32 + mf * 16 + rA;                                       \
            uint32_t off = ((uint32_t)r << 7) + (uint32_t)((k0 + ksA * 8) << 1);  \
            off ^= (r & 7) << 4;                                                  \
            LDSM_X4(rah[mf], (SB) + off);                                         \
            LDSM_X4(ral[mf], (SB) + SB_AL + off);                                 \
        }                                                                         \
        _Pragma("unroll")                                                         \
        for (int q = 0; q < 4; q++) {                                             \
            uint32_t rbh[4], rbl[4];                                              \
            int n = wn * 64 + q * 16 + nAdd;                                      \
            uint32_t off = ((uint32_t)n << 7) + (uint32_t)((k0 + kAdd) << 1);     \
            off ^= (n & 7) << 4;                                                  \
            LDSM_X4(rbh, (SB) + SB_BH + off);                                     \
            LDSM_X4(rbl, (SB) + SB_BL + off);                                     \
            mma16816(acc[0][2 * q],     rah[0], rbh[0], rbh[1]);                  \
            mma16816(acc[0][2 * q + 1], rah[0], rbh[2], rbh[3]);                  \
            mma16816(acc[1][2 * q],     rah[1], rbh[0], rbh[1]);                  \
            mma16816(acc[1][2 * q + 1], rah[1], rbh[2], rbh[3]);                  \
            mma16816(acc[0][2 * q],     rah[0], rbl[0], rbl[1]);                  \
            mma16816(acc[0][2 * q + 1], rah[0], rbl[2], rbl[3]);                  \
            mma16816(acc[1][2 * q],     rah[1], rbl[0], rbl[1]);                  \
            mma16816(acc[1][2 * q + 1], rah[1], rbl[2], rbl[3]);                  \
            mma16816(acc[0][2 * q],     ral[0], rbh[0], rbh[1]);                  \
            mma16816(acc[0][2 * q + 1], ral[0], rbh[2], rbh[3]);                  \
            mma16816(acc[1][2 * q],     ral[1], rbh[0], rbh[1]);                  \
            mma16816(acc[1][2 * q + 1], ral[1], rbh[2], rbh[3]);                  \
        }                                                                         \
    }

    CP_WAIT(1);
    __syncthreads();            // stage0 ready; idx/smsg visible
    DO_CHUNK(smB);              // chunk 0
    CP_WAIT(0);
    __syncthreads();            // stage1 ready; stage0 retired
    // prefetch x-gather into retired stage0 region [0, 64K)
    {
#pragma unroll
        for (int i0 = 0; i0 < 4096; i0 += 512) {
            int i = i0 + tid;
            int r = i >> 5, seg = i & 31;
            CP_ASYNC16(smB + (uint32_t)(r * 512 + seg * 16),
                       &g_h[(size_t)idx[r] * 128 + seg * 4]);
        }
        CP_COMMIT();
    }
    DO_CHUNK(smB + STAGE);      // chunk 1
#undef DO_CHUNK
    CP_WAIT(0);
    __syncthreads();            // xs ready

    // ---- epilogue: bias add + streaming store + fused message reduction ----
    float* xs = (float*)sm;                // [128][128] fp32
    float* smsg = (float*)(sm + OFF_MSG);  // [2][128]
    const int il = wn >> 1;                // this warp's i within the pair
#pragma unroll
    for (int mf = 0; mf < 2; mf++) {
        int r0 = wm * 32 + mf * 16 + (l >> 2);
        int row = rowBase + r0;
        float p0 = 0.0f, p1 = 0.0f;
#pragma unroll
        for (int nf = 0; nf < 8; nf++) {
            int cl = wn * 64 + nf * 8 + (l & 3) * 2;
            int col = colBase + cl;
            int jl = cl & 127;
            float b0 = bias[col], b1 = bias[col + 1];
            float t00 = acc[mf][nf][0] + b0, t01 = acc[mf][nf][1] + b1;
            float t10 = acc[mf][nf][2] + b0, t11 = acc[mf][nf][3] + b1;
            __stcs((float2*)&g_transform[(size_t)row * 16384 + col], make_float2(t00, t01));
            __stcs((float2*)&g_transform[(size_t)(row + 8) * 16384 + col], make_float2(t10, t11));
            p0 += t00 * xs[r0 * 128 + jl] + t01 * xs[r0 * 128 + jl + 1];
            p1 += t10 * xs[(r0 + 8) * 128 + jl] + t11 * xs[(r0 + 8) * 128 + jl + 1];
        }
        p0 += __shfl_xor_sync(0xffffffffu, p0, 1);
        p0 += __shfl_xor_sync(0xffffffffu, p0, 2);
        p1 += __shfl_xor_sync(0xffffffffu, p1, 1);
        p1 += __shfl_xor_sync(0xffffffffu, p1, 2);
        if ((l & 3) == 0) {
            atomicAdd(&smsg[il * 128 + r0], p0);
            atomicAdd(&smsg[il * 128 + r0 + 8], p1);
        }
    }
    __syncthreads();
    if (tid < 256) {
        int r = tid & 127, ii = tid >> 7;
        int dst = node_out[rowBase + r];
        atomicAdd(&g_upd[(size_t)dst * 128 + 2 * blockIdx.x + ii], smsg[ii * 128 + r]);
    }
}

// ---------------- message (layers 2,3): thread-per-row matvec + scatter ------
// Block = 2 edges x 128 threads; thread r computes dot(T[e,r,:], v_e) with no
// shuffles (v broadcast from SMEM), 32 independent streaming loads per thread.
__global__ void __launch_bounds__(256) k_message(const int* __restrict__ node_in,
                                                 const int* __restrict__ node_out) {
    int half = threadIdx.x >> 7;            // 0/1: which edge in this block
    int r = threadIdx.x & 127;              // output row
    int e = blockIdx.x * 2 + half;
    __shared__ float v[2][Hd];
    v[half][r] = g_h[(size_t)node_in[e] * Hd + r];
    __syncthreads();
    const float* T = &g_transform[(size_t)e * 16384 + r * 128];
    const float* vv = v[half];
    float s = 0.0f;
#pragma unroll
    for (int j = 0; j < 128; j += 4) {
        float4 tv = __ldcs((const float4*)&T[j]);
        s += tv.x * vv[j] + tv.y * vv[j + 1] + tv.z * vv[j + 2] + tv.w * vv[j + 3];
    }
    atomicAdd(&g_upd[(size_t)node_out[e] * Hd + r], s);
}

// ---------------- GRU: 16 nodes per block; re-zeroes g_upd -------------------
// If out != nullptr (last layer), also writes node_feature into the output.
__global__ void __launch_bounds__(128) k_gru(const float* __restrict__ b_ih,
                                             const float* __restrict__ b_hh,
                                             float* __restrict__ out) {
    int n0 = blockIdx.x * 16;
    int t = threadIdx.x;
    __shared__ float xs[16][Hd];
    __shared__ float hs[16][Hd];
#pragma unroll
    for (int q = 0; q < 16; q++) {
        xs[q][t] = fmaxf(g_upd[(n0 + q) * Hd + t], 0.0f);
        g_upd[(n0 + q) * Hd + t] = 0.0f;
        hs[q][t] = g_h[(n0 + q) * Hd + t];
    }
    __syncthreads();
    float ir[16], iz[16], in_[16], hr[16], hz[16], hn[16];
    float bir = b_ih[t], biz = b_ih[128 + t], bin = b_ih[256 + t];
    float bhr = b_hh[t], bhz = b_hh[128 + t], bhn = b_hh[256 + t];
#pragma unroll
    for (int q = 0; q < 16; q++) { ir[q] = bir; iz[q] = biz; in_[q] = bin; hr[q] = bhr; hz[q] = bhz; hn[q] = bhn; }
    for (int j = 0; j < Hd; j++) {
        float wi0 = g_wihT[j * 384 + t], wi1 = g_wihT[j * 384 + 128 + t], wi2 = g_wihT[j * 384 + 256 + t];
        float wh0 = g_whhT[j * 384 + t], wh1 = g_whhT[j * 384 + 128 + t], wh2 = g_whhT[j * 384 + 256 + t];
#pragma unroll
        for (int q = 0; q < 16; q++) {
            float x = xs[q][j], h = hs[q][j];
            ir[q] += x * wi0; iz[q] += x * wi1; in_[q] += x * wi2;
            hr[q] += h * wh0; hz[q] += h * wh1; hn[q] += h * wh2;
        }
    }
#pragma unroll
    for (int q = 0; q < 16; q++) {
        float r = sigm(ir[q] + hr[q]);
        float z = sigm(iz[q] + hz[q]);
        float nn = tanhf(in_[q] + r * hn[q]);
        float hv = (1.0f - z) * nn + z * hs[q][t];
        g_h[(n0 + q) * Hd + t] = hv;
        if (out) out[(size_t)(n0 + q) * Hd + t] = hv;
    }
}

// ---------------- fused Set2Set step: LSTM + attend (4 graphs/block) ---------
__global__ void __launch_bounds__(128) k_s2s(const float* __restrict__ b_ih,
        const float* __restrict__ b_hh, const int* __restrict__ n2g,
        int last, float* __restrict__ out) {
    int g0 = blockIdx.x * 4;
    int t = threadIdx.x;
    int w = t >> 5, l = t & 31;
    __shared__ float qs[4][256];
    __shared__ float hsm[4][128];
    __shared__ int seg[5];
#pragma unroll
    for (int g = 0; g < 4; g++) {
        qs[g][t] = g_qs[(g0 + g) * 256 + t];
        qs[g][128 + t] = g_qs[(g0 + g) * 256 + 128 + t];
        hsm[g][t] = g_hs[(g0 + g) * Hd + t];
    }
    if (t < 5) {
        int target = g0 + t;
        int lo = 0, hi = Nn;
        while (lo < hi) { int m = (lo + hi) >> 1; if (n2g[m] < target) lo = m + 1; else hi = m; }
        seg[t] = lo;
    }
    __syncthreads();

    // ---- LSTM for 4 graphs ----
    float gi[4], gf[4], gg[4], go[4];
    {
        float bi = b_ih[t] + b_hh[t];
        float bf = b_ih[128 + t] + b_hh[128 + t];
        float bg = b_ih[256 + t] + b_hh[256 + t];
        float bo = b_ih[384 + t] + b_hh[384 + t];
#pragma unroll
        for (int g = 0; g < 4; g++) { gi[g] = bi; gf[g] = bf; gg[g] = bg; go[g] = bo; }
    }
    for (int j = 0; j < 256; j++) {
        const float* wi = &g_lihT[j * 512];
        float w0 = wi[t], w1 = wi[128 + t], w2 = wi[256 + t], w3 = wi[384 + t];
#pragma unroll
        for (int g = 0; g < 4; g++) {
            float q = qs[g][j];
            gi[g] += q * w0; gf[g] += q * w1; gg[g] += q * w2; go[g] += q * w3;
        }
    }
    for (int j = 0; j < Hd; j++) {
        const float* wh = &g_lhhT[j * 512];
        float w0 = wh[t], w1 = wh[128 + t], w2 = wh[256 + t], w3 = wh[384 + t];
#pragma unroll
        for (int g = 0; g < 4; g++) {
            float h = hsm[g][j];
            gi[g] += h * w0; gf[g] += h * w1; gg[g] += h * w2; go[g] += h * w3;
        }
    }
    __syncthreads();      // hsm reads done before overwrite
#pragma unroll
    for (int g = 0; g < 4; g++) {
        float c = sigm(gf[g]) * g_cs[(g0 + g) * Hd + t] + sigm(gi[g]) * tanhf(gg[g]);
        float h = sigm(go[g]) * tanhf(c);
        g_cs[(g0 + g) * Hd + t] = c;
        g_hs[(g0 + g) * Hd + t] = h;
        hsm[g][t] = h;
    }
    __syncthreads();

    // ---- attend: warp w handles graph g0+w (online segment softmax) ----
    {
        int b = g0 + w;
        int lo = seg[w], hi = seg[w + 1];
        float4 hv = *(float4*)&hsm[w][l * 4];
        float m = -INFINITY, s = 0.0f;
        float p0 = 0.0f, p1 = 0.0f, p2 = 0.0f, p3 = 0.0f;
        for (int i = lo; i < hi; i++) {
            float4 nf = *(const float4*)&g_h[(size_t)i * Hd + l * 4];
            float d = hv.x * nf.x + hv.y * nf.y + hv.z * nf.z + hv.w * nf.w;
#pragma unroll
            for (int o = 16; o; o >>= 1) d += __shfl_xor_sync(0xffffffffu, d, o);
            float mn = fmaxf(m, d);
            float corr = expf(m - mn);     // exp(-inf) = 0 first iter
            float wg = expf(d - mn);
            s = s * corr + wg;
            p0 = p0 * corr + wg * nf.x; p1 = p1 * corr + wg * nf.y;
            p2 = p2 * corr + wg * nf.z; p3 = p3 * corr + wg * nf.w;
            m = mn;
        }
        float inv = (s > 0.0f) ? 1.0f / s : 0.0f;
        float4 pooled = make_float4(p0 * inv, p1 * inv, p2 * inv, p3 * inv);
        *(float4*)&g_qs[b * 256 + l * 4] = hv;
        *(float4*)&g_qs[b * 256 + 128 + l * 4] = pooled;
        if (last) {
            *(float4*)&out[b * 256 + l * 4] = hv;
            *(float4*)&out[b * 256 + 128 + l * 4] = pooled;
        }
    }
}

extern "C" void kernel_launch(void* const* d_in, const int* in_sizes, int n_in,
                              void* d_out, int out_size) {
    const int*   unit_type    = (const int*)d_in[0];
    const int*   node_in      = (const int*)d_in[1];
    const int*   node_out     = (const int*)d_in[2];
    const int*   node2graph   = (const int*)d_in[3];
    const float* edge_feature = (const float*)d_in[4];
    const float* embedding    = (const float*)d_in[5];
    const float* mlp_w1       = (const float*)d_in[6];
    const float* mlp_b1       = (const float*)d_in[7];
    const float* mlp_w2       = (const float*)d_in[8];
    const float* mlp_b2       = (const float*)d_in[9];
    const float* gru_w_ih     = (const float*)d_in[10];
    const float* gru_w_hh     = (const float*)d_in[11];
    const float* gru_b_ih     = (const float*)d_in[12];
    const float* gru_b_hh     = (const float*)d_in[13];
    const float* lstm_w_ih    = (const float*)d_in[14];
    const float* lstm_w_hh    = (const float*)d_in[15];
    const float* lstm_b_ih    = (const float*)d_in[16];
    const float* lstm_b_hh    = (const float*)d_in[17];
    float* out = (float*)d_out;

    cudaFuncSetAttribute(k_gemm_mma, cudaFuncAttributeMaxDynamicSharedMemorySize, SMEM_GEMM);

    k_init_h<<<Nn, Hd>>>(unit_type, embedding);
    k_prep<<<8128, 256>>>(mlp_w2, gru_w_ih, gru_w_hh, lstm_w_ih, lstm_w_hh);
    k_edge_hidden<<<Ee, Hd>>>(edge_feature, mlp_w1, mlp_b1);
    // GEMM + fused layer-1 message (g_upd pre-zeroed by k_prep)
    k_gemm_mma<<<dim3(64, 128), 512, SMEM_GEMM>>>(mlp_b2, node_in, node_out);
    k_gru<<<Nn / 16, Hd>>>(gru_b_ih, gru_b_hh, nullptr);

    for (int l = 1; l < 3; l++) {
        k_message<<<Ee / 2, 256>>>(node_in, node_out);
        // last GRU writes node_feature directly into the output
        k_gru<<<Nn / 16, Hd>>>(gru_b_ih, gru_b_hh, (l == 2) ? out + Bg * 256 : nullptr);
    }

    for (int s = 0; s < 3; s++) {
        k_s2s<<<Bg / 4, 128>>>(lstm_b_ih, lstm_b_hh, node2graph, s == 2, out);
    }
}

// round 13
// speedup vs baseline: 1.1597x; 1.1597x over previous
#include <cuda_runtime.h>
#include <cuda_bf16.h>
#include <cuda_fp16.h>
#include <cstdint>
#include <math.h>

// Problem constants
#define Hd   128
#define Bg   512
#define Nn   8192
#define Ee   16384
#define EDIM 32

// ---------------- scratch (device globals; no allocation) ----------------
__device__ __half g_transform[268435456];  // [E, H*H] fp16 = 512 MiB
__device__ __nv_bfloat16 g_hmid_hi[Ee * Hd];
__device__ __nv_bfloat16 g_hmid_lo[Ee * Hd];
__device__ __nv_bfloat16 g_w2T_hi[16384 * 128];   // [N, K] = W2 transposed
__device__ __nv_bfloat16 g_w2T_lo[16384 * 128];
__device__ float g_h[Nn * Hd];             // layer_input / hx  [N, 128]
__device__ float g_upd[Nn * Hd];           // scatter target     [N, 128]
__device__ float g_wihT[Hd * 384];         // gru w_ih transposed [j][t]
__device__ float g_whhT[Hd * 384];
__device__ float g_lihT[256 * 512];        // lstm w_ih transposed [j][t]
__device__ float g_lhhT[Hd * 512];
__device__ float g_hs[Bg * Hd];            // set2set h
__device__ float g_cs[Bg * Hd];            // set2set c
__device__ float g_qs[Bg * 256];           // q_star

__device__ __forceinline__ float sigm(float x) { return 1.0f / (1.0f + expf(-x)); }

__device__ __forceinline__ uint32_t smem_u32(const void* p) {
    uint32_t a;
    asm("{ .reg .u64 t; cvta.to.shared.u64 t, %1; cvt.u32.u64 %0, t; }" : "=r"(a) : "l"(p));
    return a;
}

#define LDSM_X4(r, a) \
    asm volatile("ldmatrix.sync.aligned.m8n8.x4.shared.b16 {%0,%1,%2,%3}, [%4];" \
        : "=r"((r)[0]), "=r"((r)[1]), "=r"((r)[2]), "=r"((r)[3]) : "r"(a))

__device__ __forceinline__ void mma16816(float* c, const uint32_t* a, uint32_t b0, uint32_t b1) {
    asm volatile("mma.sync.aligned.m16n8k16.row.col.f32.bf16.bf16.f32 "
        "{%0,%1,%2,%3}, {%4,%5,%6,%7}, {%8,%9}, {%0,%1,%2,%3};"
        : "+f"(c[0]), "+f"(c[1]), "+f"(c[2]), "+f"(c[3])
        : "r"(a[0]), "r"(a[1]), "r"(a[2]), "r"(a[3]), "r"(b0), "r"(b1));
}

#define CP_ASYNC16(dst, src) \
    asm volatile("cp.async.cg.shared.global [%0], [%1], 16;" :: "r"(dst), "l"(src) : "memory")
#define CP_COMMIT() asm volatile("cp.async.commit_group;" ::: "memory")
#define CP_WAIT(n)  asm volatile("cp.async.wait_group %0;" :: "n"(n) : "memory")

// ---------------- init: node embedding gather ----------------
__global__ void k_init_h(const int* __restrict__ ut, const float* __restrict__ emb) {
    int n = blockIdx.x, t = threadIdx.x;
    g_h[n * Hd + t] = emb[ut[n] * Hd + t];
}

// ---------------- prep: W2 transpose/split + weight transposes + zeroing -----
__global__ void __launch_bounds__(256) k_prep(const float* __restrict__ w2,
        const float* __restrict__ gih, const float* __restrict__ ghh,
        const float* __restrict__ lih, const float* __restrict__ lhh) {
    int bid = blockIdx.x, tid = threadIdx.x;
    if (bid < 2048) {
        __shared__ float ts[32][33];
        int kt = (bid & 3) * 32, nt = (bid >> 2) * 32;
        int r = tid >> 3, c4 = (tid & 7) * 4;
        const float4 v = *(const float4*)&w2[(size_t)(kt + r) * 16384 + nt + c4];
        ts[r][c4] = v.x; ts[r][c4 + 1] = v.y; ts[r][c4 + 2] = v.z; ts[r][c4 + 3] = v.w;
        __syncthreads();
        int n = nt + r;
        __nv_bfloat16 hi[4], lo[4];
#pragma unroll
        for (int q = 0; q < 4; q++) {
            float val = ts[c4 + q][r];
            hi[q] = __float2bfloat16(val);
            lo[q] = __float2bfloat16(val - __bfloat162float(hi[q]));
        }
        *(uint2*)&g_w2T_hi[(size_t)n * 128 + kt + c4] = *(uint2*)hi;
        *(uint2*)&g_w2T_lo[(size_t)n * 128 + kt + c4] = *(uint2*)lo;
        return;
    }
    long i = (long)(bid - 2048) * 256 + tid;
    if (i < 49152) { int t = i / 128, j = i % 128; g_wihT[j * 384 + t] = gih[i]; g_whhT[j * 384 + t] = ghh[i]; return; }
    i -= 49152;
    if (i < 131072) { int t = i / 256, j = i % 256; g_lihT[j * 512 + t] = lih[i]; return; }
    i -= 131072;
    if (i < 65536) { int t = i / 128, j = i % 128; g_lhhT[j * 512 + t] = lhh[i]; return; }
    i -= 65536;
    if (i < Nn * Hd) { g_upd[i] = 0.0f; return; }
    i -= Nn * Hd;
    if (i < Bg * Hd) { g_hs[i] = 0.0f; return; }
    i -= Bg * Hd;
    if (i < Bg * Hd) { g_cs[i] = 0.0f; return; }
    i -= Bg * Hd;
    if (i < Bg * 256) { g_qs[i] = 0.0f; return; }
}

// ---------------- edge hidden: hmid = relu(ef @ W1 + b1), split to bf16 hi/lo
__global__ void k_edge_hidden(const float* __restrict__ ef, const float* __restrict__ w1,
                              const float* __restrict__ b1) {
    int e = blockIdx.x, t = threadIdx.x;
    __shared__ float efs[EDIM];
    if (t < EDIM) efs[t] = ef[e * EDIM + t];
    __syncthreads();
    float acc = b1[t];
#pragma unroll
    for (int k = 0; k < EDIM; k++) acc += efs[k] * w1[k * Hd + t];
    acc = fmaxf(acc, 0.0f);
    __nv_bfloat16 hi = __float2bfloat16(acc);
    float r = acc - __bfloat162float(hi);
    g_hmid_hi[e * Hd + t] = hi;
    g_hmid_lo[e * Hd + t] = __float2bfloat16(r);
}

// ---------------- cp.async-pipelined mma.sync GEMM + fused layer-1 message --
#define STAGE 98304
#define SB_AL 16384
#define SB_BH 32768
#define SB_BL 65536
#define OFF_MSG 196608
#define OFF_IDX 197632
#define SMEM_GEMM 198144
__global__ void __launch_bounds__(512, 1) k_gemm_mma(const float* __restrict__ bias,
        const int* __restrict__ node_in, const int* __restrict__ node_out) {
    extern __shared__ char sm[];
    const int tid = threadIdx.x;
    const int wid = tid >> 5, l = tid & 31;
    const int wm = wid & 3, wn = wid >> 2;            // 4 x 4 warp grid
    const int rowBase = blockIdx.y * 128;
    const int colBase = blockIdx.x * 256;
    const uint32_t smB = smem_u32(sm);
    int* idx = (int*)(sm + OFF_IDX);

    // issue both K-chunk stages
#pragma unroll
    for (int s = 0; s < 2; s++) {
        const uint32_t sb = smB + s * STAGE;
        const int kOff = s * 64;
#pragma unroll
        for (int i0 = 0; i0 < 1024; i0 += 512) {
            int i = i0 + tid;
            int r = i >> 3, kk = i & 7;
            uint32_t off = ((uint32_t)r << 7) + ((uint32_t)kk << 4);
            off ^= (r & 7) << 4;
            const size_t gi = (size_t)(rowBase + r) * 128 + kOff + kk * 8;
            CP_ASYNC16(sb + off, &g_hmid_hi[gi]);
            CP_ASYNC16(sb + SB_AL + off, &g_hmid_lo[gi]);
        }
#pragma unroll
        for (int i0 = 0; i0 < 2048; i0 += 512) {
            int i = i0 + tid;
            int r = i >> 3, kk = i & 7;
            uint32_t off = ((uint32_t)r << 7) + ((uint32_t)kk << 4);
            off ^= (r & 7) << 4;
            const size_t gi = (size_t)(colBase + r) * 128 + kOff + kk * 8;
            CP_ASYNC16(sb + SB_BH + off, &g_w2T_hi[gi]);
            CP_ASYNC16(sb + SB_BL + off, &g_w2T_lo[gi]);
        }
        CP_COMMIT();
    }
    if (tid < 128) idx[tid] = node_in[rowBase + tid];
    if (tid >= 256 && tid < 512) ((float*)(sm + OFF_MSG))[tid - 256] = 0.0f;

    float acc[2][8][4];
#pragma unroll
    for (int mf = 0; mf < 2; mf++)
#pragma unroll
        for (int nf = 0; nf < 8; nf++)
#pragma unroll
            for (int q = 0; q < 4; q++) acc[mf][nf][q] = 0.0f;

    const int rA = l & 15;
    const int ksA = (l >> 4) & 1;
    const int nAdd = (l & 7) + ((l >> 4) << 3);
    const int kAdd = ((l >> 3) & 1) << 3;

#define DO_CHUNK(SB)                                                              \
    _Pragma("unroll")                                                             \
    for (int ks = 0; ks < 4; ks++) {                                              \
        const int k0 = ks * 16;                                                   \
        uint32_t rah[2][4], ral[2][4];                                            \
        _Pragma("unroll")                                                         \
        for (int mf = 0; mf < 2; mf++) {                                          \
            int r = wm * 32 + mf * 16 + rA;                                       \
            uint32_t off = ((uint32_t)r << 7) + (uint32_t)((k0 + ksA * 8) << 1);  \
            off ^= (r & 7) << 4;                                                  \
            LDSM_X4(rah[mf], (SB) + off);                                         \
            LDSM_X4(ral[mf], (SB) + SB_AL + off);                                 \
        }                                                                         \
        _Pragma("unroll")                                                         \
        for (int q = 0; q < 4; q++) {                                             \
            uint32_t rbh[4], rbl[4];                                              \
            int n = wn * 64 + q * 16 + nAdd;                                      \
            uint32_t off = ((uint32_t)n << 7) + (uint32_t)((k0 + kAdd) << 1);     \
            off ^= (n & 7) << 4;                                                  \
            LDSM_X4(rbh, (SB) + SB_BH + off);                                     \
            LDSM_X4(rbl, (SB) + SB_BL + off);                                     \
            _Pragma("unroll")                                                     \
            for (int mf = 0; mf < 2; mf++) {                                      \
                mma16816(acc[mf][2 * q],     rah[mf], rbh[0], rbh[1]);            \
                mma16816(acc[mf][2 * q + 1], rah[mf], rbh[2], rbh[3]);            \
                mma16816(acc[mf][2 * q],     rah[mf], rbl[0], rbl[1]);            \
                mma16816(acc[mf][2 * q + 1], rah[mf], rbl[2], rbl[3]);            \
                mma16816(acc[mf][2 * q],     ral[mf], rbh[0], rbh[1]);            \
                mma16816(acc[mf][2 * q + 1], ral[mf], rbh[2], rbh[3]);            \
            }                                                                     \
        }                                                                         \
    }

    CP_WAIT(1);
    __syncthreads();            // stage0 ready; idx/smsg visible
    DO_CHUNK(smB);              // chunk 0
    CP_WAIT(0);
    __syncthreads();            // stage1 ready; stage0 retired
    // prefetch x-gather into retired stage0 region [0, 64K)
    {
#pragma unroll
        for (int i0 = 0; i0 < 4096; i0 += 512) {
            int i = i0 + tid;
            int r = i >> 5, seg = i & 31;
            CP_ASYNC16(smB + (uint32_t)(r * 512 + seg * 16),
                       &g_h[(size_t)idx[r] * 128 + seg * 4]);
        }
        CP_COMMIT();
    }
    DO_CHUNK(smB + STAGE);      // chunk 1
#undef DO_CHUNK
    CP_WAIT(0);
    __syncthreads();            // xs ready

    // ---- epilogue: bias add + fp16 streaming store + fused message ----
    float* xs = (float*)sm;                // [128][128] fp32
    float* smsg = (float*)(sm + OFF_MSG);  // [2][128]
    const int il = wn >> 1;                // this warp's i within the pair
#pragma unroll
    for (int mf = 0; mf < 2; mf++) {
        int r0 = wm * 32 + mf * 16 + (l >> 2);
        int row = rowBase + r0;
        float p0 = 0.0f, p1 = 0.0f;
#pragma unroll
        for (int nf = 0; nf < 8; nf++) {
            int cl = wn * 64 + nf * 8 + (l & 3) * 2;
            int col = colBase + cl;
            int jl = cl & 127;
            float b0 = bias[col], b1 = bias[col + 1];
            float t00 = acc[mf][nf][0] + b0, t01 = acc[mf][nf][1] + b1;
            float t10 = acc[mf][nf][2] + b0, t11 = acc[mf][nf][3] + b1;
            __half2 h0 = __floats2half2_rn(t00, t01);
            __half2 h1 = __floats2half2_rn(t10, t11);
            __stcs((uint32_t*)&g_transform[(size_t)row * 16384 + col], *(uint32_t*)&h0);
            __stcs((uint32_t*)&g_transform[(size_t)(row + 8) * 16384 + col], *(uint32_t*)&h1);
            p0 += t00 * xs[r0 * 128 + jl] + t01 * xs[r0 * 128 + jl + 1];
            p1 += t10 * xs[(r0 + 8) * 128 + jl] + t11 * xs[(r0 + 8) * 128 + jl + 1];
        }
        p0 += __shfl_xor_sync(0xffffffffu, p0, 1);
        p0 += __shfl_xor_sync(0xffffffffu, p0, 2);
        p1 += __shfl_xor_sync(0xffffffffu, p1, 1);
        p1 += __shfl_xor_sync(0xffffffffu, p1, 2);
        if ((l & 3) == 0) {
            atomicAdd(&smsg[il * 128 + r0], p0);
            atomicAdd(&smsg[il * 128 + r0 + 8], p1);
        }
    }
    __syncthreads();
    if (tid < 256) {
        int r = tid & 127, ii = tid >> 7;
        int dst = node_out[rowBase + r];
        atomicAdd(&g_upd[(size_t)dst * 128 + 2 * blockIdx.x + ii], smsg[ii * 128 + r]);
    }
}

// ---------------- message (layers 2,3): warp-per-row matvec, fp16 transform --
__global__ void k_message(const int* __restrict__ node_in, const int* __restrict__ node_out) {
    int e = blockIdx.x, t = threadIdx.x;
    __shared__ float v[Hd];
    int src = node_in[e];
    v[t] = g_h[src * Hd + t];
    __syncthreads();
    int lane = t & 31, w = t >> 5;
    int dst = node_out[e];
    const __half* T = &g_transform[(size_t)e * 16384];
    float v0 = v[lane * 4 + 0], v1 = v[lane * 4 + 1], v2 = v[lane * 4 + 2], v3 = v[lane * 4 + 3];
#pragma unroll
    for (int r = w; r < Hd; r += 4) {
        uint2 raw = __ldcs((const uint2*)&T[r * 128 + lane * 4]);
        float2 a = __half22float2(*(__half2*)&raw.x);
        float2 b = __half22float2(*(__half2*)&raw.y);
        float s = a.x * v0 + a.y * v1 + b.x * v2 + b.y * v3;
#pragma unroll
        for (int o = 16; o; o >>= 1) s += __shfl_down_sync(0xffffffffu, s, o);
        if (lane == 0) atomicAdd(&g_upd[dst * Hd + r], s);
    }
}

// ---------------- GRU: 16 nodes per block; re-zeroes g_upd -------------------
// If out != nullptr (last layer), also writes node_feature into the output.
__global__ void __launch_bounds__(128) k_gru(const float* __restrict__ b_ih,
                                             const float* __restrict__ b_hh,
                                             float* __restrict__ out) {
    int n0 = blockIdx.x * 16;
    int t = threadIdx.x;
    __shared__ float xs[16][Hd];
    __shared__ float hs[16][Hd];
#pragma unroll
    for (int q = 0; q < 16; q++) {
        xs[q][t] = fmaxf(g_upd[(n0 + q) * Hd + t], 0.0f);
        g_upd[(n0 + q) * Hd + t] = 0.0f;
        hs[q][t] = g_h[(n0 + q) * Hd + t];
    }
    __syncthreads();
    float ir[16], iz[16], in_[16], hr[16], hz[16], hn[16];
    float bir = b_ih[t], biz = b_ih[128 + t], bin = b_ih[256 + t];
    float bhr = b_hh[t], bhz = b_hh[128 + t], bhn = b_hh[256 + t];
#pragma unroll
    for (int q = 0; q < 16; q++) { ir[q] = bir; iz[q] = biz; in_[q] = bin; hr[q] = bhr; hz[q] = bhz; hn[q] = bhn; }
    for (int j = 0; j < Hd; j++) {
        float wi0 = g_wihT[j * 384 + t], wi1 = g_wihT[j * 384 + 128 + t], wi2 = g_wihT[j * 384 + 256 + t];
        float wh0 = g_whhT[j * 384 + t], wh1 = g_whhT[j * 384 + 128 + t], wh2 = g_whhT[j * 384 + 256 + t];
#pragma unroll
        for (int q = 0; q < 16; q++) {
            float x = xs[q][j], h = hs[q][j];
            ir[q] += x * wi0; iz[q] += x * wi1; in_[q] += x * wi2;
            hr[q] += h * wh0; hz[q] += h * wh1; hn[q] += h * wh2;
        }
    }
#pragma unroll
    for (int q = 0; q < 16; q++) {
        float r = sigm(ir[q] + hr[q]);
        float z = sigm(iz[q] + hz[q]);
        float nn = tanhf(in_[q] + r * hn[q]);
        float hv = (1.0f - z) * nn + z * hs[q][t];
        g_h[(n0 + q) * Hd + t] = hv;
        if (out) out[(size_t)(n0 + q) * Hd + t] = hv;
    }
}

// ---------------- fused Set2Set step: LSTM + attend (4 graphs/block) ---------
__global__ void __launch_bounds__(128) k_s2s(const float* __restrict__ b_ih,
        const float* __restrict__ b_hh, const int* __restrict__ n2g,
        int last, float* __restrict__ out) {
    int g0 = blockIdx.x * 4;
    int t = threadIdx.x;
    int w = t >> 5, l = t & 31;
    __shared__ float qs[4][256];
    __shared__ float hsm[4][128];
    __shared__ int seg[5];
#pragma unroll
    for (int g = 0; g < 4; g++) {
        qs[g][t] = g_qs[(g0 + g) * 256 + t];
        qs[g][128 + t] = g_qs[(g0 + g) * 256 + 128 + t];
        hsm[g][t] = g_hs[(g0 + g) * Hd + t];
    }
    if (t < 5) {
        int target = g0 + t;
        int lo = 0, hi = Nn;
        while (lo < hi) { int m = (lo + hi) >> 1; if (n2g[m] < target) lo = m + 1; else hi = m; }
        seg[t] = lo;
    }
    __syncthreads();

    // ---- LSTM for 4 graphs ----
    float gi[4], gf[4], gg[4], go[4];
    {
        float bi = b_ih[t] + b_hh[t];
        float bf = b_ih[128 + t] + b_hh[128 + t];
        float bg = b_ih[256 + t] + b_hh[256 + t];
        float bo = b_ih[384 + t] + b_hh[384 + t];
#pragma unroll
        for (int g = 0; g < 4; g++) { gi[g] = bi; gf[g] = bf; gg[g] = bg; go[g] = bo; }
    }
    for (int j = 0; j < 256; j++) {
        const float* wi = &g_lihT[j * 512];
        float w0 = wi[t], w1 = wi[128 + t], w2 = wi[256 + t], w3 = wi[384 + t];
#pragma unroll
        for (int g = 0; g < 4; g++) {
            float q = qs[g][j];
            gi[g] += q * w0; gf[g] += q * w1; gg[g] += q * w2; go[g] += q * w3;
        }
    }
    for (int j = 0; j < Hd; j++) {
        const float* wh = &g_lhhT[j * 512];
        float w0 = wh[t], w1 = wh[128 + t], w2 = wh[256 + t], w3 = wh[384 + t];
#pragma unroll
        for (int g = 0; g < 4; g++) {
            float h = hsm[g][j];
            gi[g] += h * w0; gf[g] += h * w1; gg[g] += h * w2; go[g] += h * w3;
        }
    }
    __syncthreads();      // hsm reads done before overwrite
#pragma unroll
    for (int g = 0; g < 4; g++) {
        float c = sigm(gf[g]) * g_cs[(g0 + g) * Hd + t] + sigm(gi[g]) * tanhf(gg[g]);
        float h = sigm(go[g]) * tanhf(c);
        g_cs[(g0 + g) * Hd + t] = c;
        g_hs[(g0 + g) * Hd + t] = h;
        hsm[g][t] = h;
    }
    __syncthreads();

    // ---- attend: warp w handles graph g0+w (online segment softmax) ----
    {
        int b = g0 + w;
        int lo = seg[w], hi = seg[w + 1];
        float4 hv = *(float4*)&hsm[w][l * 4];
        float m = -INFINITY, s = 0.0f;
        float p0 = 0.0f, p1 = 0.0f, p2 = 0.0f, p3 = 0.0f;
        for (int i = lo; i < hi; i++) {
            float4 nf = *(const float4*)&g_h[(size_t)i * Hd + l * 4];
            float d = hv.x * nf.x + hv.y * nf.y + hv.z * nf.z + hv.w * nf.w;
#pragma unroll
            for (int o = 16; o; o >>= 1) d += __shfl_xor_sync(0xffffffffu, d, o);
            float mn = fmaxf(m, d);
            float corr = expf(m - mn);     // exp(-inf) = 0 first iter
            float wg = expf(d - mn);
            s = s * corr + wg;
            p0 = p0 * corr + wg * nf.x; p1 = p1 * corr + wg * nf.y;
            p2 = p2 * corr + wg * nf.z; p3 = p3 * corr + wg * nf.w;
            m = mn;
        }
        float inv = (s > 0.0f) ? 1.0f / s : 0.0f;
        float4 pooled = make_float4(p0 * inv, p1 * inv, p2 * inv, p3 * inv);
        *(float4*)&g_qs[b * 256 + l * 4] = hv;
        *(float4*)&g_qs[b * 256 + 128 + l * 4] = pooled;
        if (last) {
            *(float4*)&out[b * 256 + l * 4] = hv;
            *(float4*)&out[b * 256 + 128 + l * 4] = pooled;
        }
    }
}

extern "C" void kernel_launch(void* const* d_in, const int* in_sizes, int n_in,
                              void* d_out, int out_size) {
    const int*   unit_type    = (const int*)d_in[0];
    const int*   node_in      = (const int*)d_in[1];
    const int*   node_out     = (const int*)d_in[2];
    const int*   node2graph   = (const int*)d_in[3];
    const float* edge_feature = (const float*)d_in[4];
    const float* embedding    = (const float*)d_in[5];
    const float* mlp_w1       = (const float*)d_in[6];
    const float* mlp_b1       = (const float*)d_in[7];
    const float* mlp_w2       = (const float*)d_in[8];
    const float* mlp_b2       = (const float*)d_in[9];
    const float* gru_w_ih     = (const float*)d_in[10];
    const float* gru_w_hh     = (const float*)d_in[11];
    const float* gru_b_ih     = (const float*)d_in[12];
    const float* gru_b_hh     = (const float*)d_in[13];
    const float* lstm_w_ih    = (const float*)d_in[14];
    const float* lstm_w_hh    = (const float*)d_in[15];
    const float* lstm_b_ih    = (const float*)d_in[16];
    const float* lstm_b_hh    = (const float*)d_in[17];
    float* out = (float*)d_out;

    cudaFuncSetAttribute(k_gemm_mma, cudaFuncAttributeMaxDynamicSharedMemorySize, SMEM_GEMM);

    k_init_h<<<Nn, Hd>>>(unit_type, embedding);
    k_prep<<<8128, 256>>>(mlp_w2, gru_w_ih, gru_w_hh, lstm_w_ih, lstm_w_hh);
    k_edge_hidden<<<Ee, Hd>>>(edge_feature, mlp_w1, mlp_b1);
    // GEMM + fused layer-1 message (g_upd pre-zeroed by k_prep)
    k_gemm_mma<<<dim3(64, 128), 512, SMEM_GEMM>>>(mlp_b2, node_in, node_out);
    k_gru<<<Nn / 16, Hd>>>(gru_b_ih, gru_b_hh, nullptr);

    for (int l = 1; l < 3; l++) {
        k_message<<<Ee, Hd>>>(node_in, node_out);
        // last GRU writes node_feature directly into the output
        k_gru<<<Nn / 16, Hd>>>(gru_b_ih, gru_b_hh, (l == 2) ? out + Bg * 256 : nullptr);
    }

    for (int s = 0; s < 3; s++) {
        k_s2s<<<Bg / 4, 128>>>(lstm_b_ih, lstm_b_hh, node2graph, s == 2, out);
    }
}

// round 14
// speedup vs baseline: 1.3837x; 1.1931x over previous
#include <cuda_runtime.h>
#include <cuda_bf16.h>
#include <cuda_fp16.h>
#include <cstdint>
#include <math.h>

// Problem constants
#define Hd   128
#define Bg   512
#define Nn   8192
#define Ee   16384
#define EDIM 32

// ---------------- scratch (device globals; no allocation) ----------------
__device__ __half g_transform[268435456];  // [E, H*H] fp16 = 512 MiB
__device__ __half g_hmid[Ee * Hd];         // fp16 edge hidden
__device__ __half g_w2T[16384 * 128];      // [N, K] = W2 transposed, fp16
__device__ float g_h[Nn * Hd];             // layer_input / hx  [N, 128]
__device__ float g_upd[Nn * Hd];           // scatter target     [N, 128]
__device__ float g_wihT[Hd * 384];         // gru w_ih transposed [j][t]
__device__ float g_whhT[Hd * 384];
__device__ float g_lihT[256 * 512];        // lstm w_ih transposed [j][t]
__device__ float g_lhhT[Hd * 512];
__device__ float g_hs[Bg * Hd];            // set2set h
__device__ float g_cs[Bg * Hd];            // set2set c
__device__ float g_qs[Bg * 256];           // q_star

__device__ __forceinline__ float sigm(float x) { return 1.0f / (1.0f + expf(-x)); }

__device__ __forceinline__ uint32_t smem_u32(const void* p) {
    uint32_t a;
    asm("{ .reg .u64 t; cvta.to.shared.u64 t, %1; cvt.u32.u64 %0, t; }" : "=r"(a) : "l"(p));
    return a;
}

#define LDSM_X4(r, a) \
    asm volatile("ldmatrix.sync.aligned.m8n8.x4.shared.b16 {%0,%1,%2,%3}, [%4];" \
        : "=r"((r)[0]), "=r"((r)[1]), "=r"((r)[2]), "=r"((r)[3]) : "r"(a))

__device__ __forceinline__ void mma16816h(float* c, const uint32_t* a, uint32_t b0, uint32_t b1) {
    asm volatile("mma.sync.aligned.m16n8k16.row.col.f32.f16.f16.f32 "
        "{%0,%1,%2,%3}, {%4,%5,%6,%7}, {%8,%9}, {%0,%1,%2,%3};"
        : "+f"(c[0]), "+f"(c[1]), "+f"(c[2]), "+f"(c[3])
        : "r"(a[0]), "r"(a[1]), "r"(a[2]), "r"(a[3]), "r"(b0), "r"(b1));
}

#define CP_ASYNC16(dst, src) \
    asm volatile("cp.async.cg.shared.global [%0], [%1], 16;" :: "r"(dst), "l"(src) : "memory")
#define CP_COMMIT() asm volatile("cp.async.commit_group;" ::: "memory")
#define CP_WAIT(n)  asm volatile("cp.async.wait_group %0;" :: "n"(n) : "memory")

// ---------------- init: node embedding gather ----------------
__global__ void k_init_h(const int* __restrict__ ut, const float* __restrict__ emb) {
    int n = blockIdx.x, t = threadIdx.x;
    g_h[n * Hd + t] = emb[ut[n] * Hd + t];
}

// ---------------- prep: W2 transpose (fp16) + weight transposes + zeroing ----
__global__ void __launch_bounds__(256) k_prep(const float* __restrict__ w2,
        const float* __restrict__ gih, const float* __restrict__ ghh,
        const float* __restrict__ lih, const float* __restrict__ lhh) {
    int bid = blockIdx.x, tid = threadIdx.x;
    if (bid < 2048) {
        __shared__ float ts[32][33];
        int kt = (bid & 3) * 32, nt = (bid >> 2) * 32;
        int r = tid >> 3, c4 = (tid & 7) * 4;
        const float4 v = *(const float4*)&w2[(size_t)(kt + r) * 16384 + nt + c4];
        ts[r][c4] = v.x; ts[r][c4 + 1] = v.y; ts[r][c4 + 2] = v.z; ts[r][c4 + 3] = v.w;
        __syncthreads();
        int n = nt + r;
        __half h4[4];
#pragma unroll
        for (int q = 0; q < 4; q++) h4[q] = __float2half(ts[c4 + q][r]);
        *(uint2*)&g_w2T[(size_t)n * 128 + kt + c4] = *(uint2*)h4;
        return;
    }
    long i = (long)(bid - 2048) * 256 + tid;
    if (i < 49152) { int t = i / 128, j = i % 128; g_wihT[j * 384 + t] = gih[i]; g_whhT[j * 384 + t] = ghh[i]; return; }
    i -= 49152;
    if (i < 131072) { int t = i / 256, j = i % 256; g_lihT[j * 512 + t] = lih[i]; return; }
    i -= 131072;
    if (i < 65536) { int t = i / 128, j = i % 128; g_lhhT[j * 512 + t] = lhh[i]; return; }
    i -= 65536;
    if (i < Nn * Hd) { g_upd[i] = 0.0f; return; }
    i -= Nn * Hd;
    if (i < Bg * Hd) { g_hs[i] = 0.0f; return; }
    i -= Bg * Hd;
    if (i < Bg * Hd) { g_cs[i] = 0.0f; return; }
    i -= Bg * Hd;
    if (i < Bg * 256) { g_qs[i] = 0.0f; return; }
}

// ---------------- edge hidden: hmid = relu(ef @ W1 + b1) -> fp16 -------------
__global__ void k_edge_hidden(const float* __restrict__ ef, const float* __restrict__ w1,
                              const float* __restrict__ b1) {
    int e = blockIdx.x, t = threadIdx.x;
    __shared__ float efs[EDIM];
    if (t < EDIM) efs[t] = ef[e * EDIM + t];
    __syncthreads();
    float acc = b1[t];
#pragma unroll
    for (int k = 0; k < EDIM; k++) acc += efs[k] * w1[k * Hd + t];
    g_hmid[e * Hd + t] = __float2half(fmaxf(acc, 0.0f));
}

// ---------------- cp.async-pipelined fp16 mma GEMM + fused layer-1 message --
// Block 128(edges) x 256(cols). 16 warps 4x4, warp tile 32x64.
// Single-pass fp16: 6 LDSM.x4 -> 16 MMA per warp-kstep.
// K split into two 64-chunks: 2 stages x 48 KB {A 16K | B 32K}.
// x-gather prefetched into a dedicated 64 KB region as cp.async group 3.
#define STAGE 49152
#define SB_B  16384
#define OFF_X 98304
#define OFF_MSG 163840
#define OFF_IDX 164864
#define SMEM_GEMM 165376
__global__ void __launch_bounds__(512, 1) k_gemm_mma(const float* __restrict__ bias,
        const int* __restrict__ node_in, const int* __restrict__ node_out) {
    extern __shared__ char sm[];
    const int tid = threadIdx.x;
    const int wid = tid >> 5, l = tid & 31;
    const int wm = wid & 3, wn = wid >> 2;            // 4 x 4 warp grid
    const int rowBase = blockIdx.y * 128;
    const int colBase = blockIdx.x * 256;
    const uint32_t smB = smem_u32(sm);
    int* idx = (int*)(sm + OFF_IDX);

    // issue both K-chunk stages (groups 0, 1)
#pragma unroll
    for (int s = 0; s < 2; s++) {
        const uint32_t sb = smB + s * STAGE;
        const int kOff = s * 64;
#pragma unroll
        for (int i0 = 0; i0 < 1024; i0 += 512) {
            int i = i0 + tid;
            int r = i >> 3, kk = i & 7;
            uint32_t off = ((uint32_t)r << 7) + ((uint32_t)kk << 4);
            off ^= (r & 7) << 4;
            CP_ASYNC16(sb + off, &g_hmid[(size_t)(rowBase + r) * 128 + kOff + kk * 8]);
        }
#pragma unroll
        for (int i0 = 0; i0 < 2048; i0 += 512) {
            int i = i0 + tid;
            int r = i >> 3, kk = i & 7;
            uint32_t off = ((uint32_t)r << 7) + ((uint32_t)kk << 4);
            off ^= (r & 7) << 4;
            CP_ASYNC16(sb + SB_B + off, &g_w2T[(size_t)(colBase + r) * 128 + kOff + kk * 8]);
        }
        CP_COMMIT();
    }
    if (tid < 128) idx[tid] = node_in[rowBase + tid];
    if (tid >= 256 && tid < 512) ((float*)(sm + OFF_MSG))[tid - 256] = 0.0f;
    __syncthreads();            // idx visible for x-gather issue

    // x-gather into dedicated region (group 2) — hidden behind both chunks
#pragma unroll
    for (int i0 = 0; i0 < 4096; i0 += 512) {
        int i = i0 + tid;
        int r = i >> 5, seg = i & 31;
        CP_ASYNC16(smB + OFF_X + (uint32_t)(r * 512 + seg * 16),
                   &g_h[(size_t)idx[r] * 128 + seg * 4]);
    }
    CP_COMMIT();

    float acc[2][8][4];
#pragma unroll
    for (int mf = 0; mf < 2; mf++)
#pragma unroll
        for (int nf = 0; nf < 8; nf++)
#pragma unroll
            for (int q = 0; q < 4; q++) acc[mf][nf][q] = 0.0f;

    const int rA = l & 15;
    const int ksA = (l >> 4) & 1;
    const int nAdd = (l & 7) + ((l >> 4) << 3);
    const int kAdd = ((l >> 3) & 1) << 3;

#define DO_CHUNK(SB)                                                              \
    _Pragma("unroll")                                                             \
    for (int ks = 0; ks < 4; ks++) {                                              \
        const int k0 = ks * 16;                                                   \
        uint32_t ra[2][4];                                                        \
        _Pragma("unroll")                                                         \
        for (int mf = 0; mf < 2; mf++) {                                          \
            int r = wm * 32 + mf * 16 + rA;                                       \
            uint32_t off = ((uint32_t)r << 7) + (uint32_t)((k0 + ksA * 8) << 1);  \
            off ^= (r & 7) << 4;                                                  \
            LDSM_X4(ra[mf], (SB) + off);                                          \
        }                                                                         \
        _Pragma("unroll")                                                         \
        for (int q = 0; q < 4; q++) {                                             \
            uint32_t rb[4];                                                       \
            int n = wn * 64 + q * 16 + nAdd;                                      \
            uint32_t off = ((uint32_t)n << 7) + (uint32_t)((k0 + kAdd) << 1);     \
            off ^= (n & 7) << 4;                                                  \
            LDSM_X4(rb, (SB) + SB_B + off);                                       \
            _Pragma("unroll")                                                     \
            for (int mf = 0; mf < 2; mf++) {                                      \
                mma16816h(acc[mf][2 * q],     ra[mf], rb[0], rb[1]);              \
                mma16816h(acc[mf][2 * q + 1], ra[mf], rb[2], rb[3]);              \
            }                                                                     \
        }                                                                         \
    }

    CP_WAIT(2);
    __syncthreads();            // stage0 ready
    DO_CHUNK(smB);              // chunk 0
    CP_WAIT(1);
    __syncthreads();            // stage1 ready
    DO_CHUNK(smB + STAGE);      // chunk 1
#undef DO_CHUNK
    CP_WAIT(0);
    __syncthreads();            // xs ready

    // ---- epilogue: bias add + fp16 streaming store + fused message ----
    float* xs = (float*)(sm + OFF_X);      // [128][128] fp32
    float* smsg = (float*)(sm + OFF_MSG);  // [2][128]
    const int il = wn >> 1;                // this warp's i within the pair
#pragma unroll
    for (int mf = 0; mf < 2; mf++) {
        int r0 = wm * 32 + mf * 16 + (l >> 2);
        int row = rowBase + r0;
        float p0 = 0.0f, p1 = 0.0f;
#pragma unroll
        for (int nf = 0; nf < 8; nf++) {
            int cl = wn * 64 + nf * 8 + (l & 3) * 2;
            int col = colBase + cl;
            int jl = cl & 127;
            float b0 = bias[col], b1 = bias[col + 1];
            float t00 = acc[mf][nf][0] + b0, t01 = acc[mf][nf][1] + b1;
            float t10 = acc[mf][nf][2] + b0, t11 = acc[mf][nf][3] + b1;
            __half2 h0 = __floats2half2_rn(t00, t01);
            __half2 h1 = __floats2half2_rn(t10, t11);
            __stcs((uint32_t*)&g_transform[(size_t)row * 16384 + col], *(uint32_t*)&h0);
            __stcs((uint32_t*)&g_transform[(size_t)(row + 8) * 16384 + col], *(uint32_t*)&h1);
            p0 += t00 * xs[r0 * 128 + jl] + t01 * xs[r0 * 128 + jl + 1];
            p1 += t10 * xs[(r0 + 8) * 128 + jl] + t11 * xs[(r0 + 8) * 128 + jl + 1];
        }
        p0 += __shfl_xor_sync(0xffffffffu, p0, 1);
        p0 += __shfl_xor_sync(0xffffffffu, p0, 2);
        p1 += __shfl_xor_sync(0xffffffffu, p1, 1);
        p1 += __shfl_xor_sync(0xffffffffu, p1, 2);
        if ((l & 3) == 0) {
            atomicAdd(&smsg[il * 128 + r0], p0);
            atomicAdd(&smsg[il * 128 + r0 + 8], p1);
        }
    }
    __syncthreads();
    if (tid < 256) {
        int r = tid & 127, ii = tid >> 7;
        int dst = node_out[rowBase + r];
        atomicAdd(&g_upd[(size_t)dst * 128 + 2 * blockIdx.x + ii], smsg[ii * 128 + r]);
    }
}

// ---------------- message (layers 2,3): warp-per-row matvec, fp16 transform --
__global__ void k_message(const int* __restrict__ node_in, const int* __restrict__ node_out) {
    int e = blockIdx.x, t = threadIdx.x;
    __shared__ float v[Hd];
    int src = node_in[e];
    v[t] = g_h[src * Hd + t];
    __syncthreads();
    int lane = t & 31, w = t >> 5;
    int dst = node_out[e];
    const __half* T = &g_transform[(size_t)e * 16384];
    float v0 = v[lane * 4 + 0], v1 = v[lane * 4 + 1], v2 = v[lane * 4 + 2], v3 = v[lane * 4 + 3];
#pragma unroll
    for (int r = w; r < Hd; r += 4) {
        uint2 raw = __ldcs((const uint2*)&T[r * 128 + lane * 4]);
        float2 a = __half22float2(*(__half2*)&raw.x);
        float2 b = __half22float2(*(__half2*)&raw.y);
        float s = a.x * v0 + a.y * v1 + b.x * v2 + b.y * v3;
#pragma unroll
        for (int o = 16; o; o >>= 1) s += __shfl_down_sync(0xffffffffu, s, o);
        if (lane == 0) atomicAdd(&g_upd[dst * Hd + r], s);
    }
}

// ---------------- GRU: 16 nodes per block; re-zeroes g_upd -------------------
__global__ void __launch_bounds__(128) k_gru(const float* __restrict__ b_ih,
                                             const float* __restrict__ b_hh,
                                             float* __restrict__ out) {
    int n0 = blockIdx.x * 16;
    int t = threadIdx.x;
    __shared__ float xs[16][Hd];
    __shared__ float hs[16][Hd];
#pragma unroll
    for (int q = 0; q < 16; q++) {
        xs[q][t] = fmaxf(g_upd[(n0 + q) * Hd + t], 0.0f);
        g_upd[(n0 + q) * Hd + t] = 0.0f;
        hs[q][t] = g_h[(n0 + q) * Hd + t];
    }
    __syncthreads();
    float ir[16], iz[16], in_[16], hr[16], hz[16], hn[16];
    float bir = b_ih[t], biz = b_ih[128 + t], bin = b_ih[256 + t];
    float bhr = b_hh[t], bhz = b_hh[128 + t], bhn = b_hh[256 + t];
#pragma unroll
    for (int q = 0; q < 16; q++) { ir[q] = bir; iz[q] = biz; in_[q] = bin; hr[q] = bhr; hz[q] = bhz; hn[q] = bhn; }
    for (int j = 0; j < Hd; j++) {
        float wi0 = g_wihT[j * 384 + t], wi1 = g_wihT[j * 384 + 128 + t], wi2 = g_wihT[j * 384 + 256 + t];
        float wh0 = g_whhT[j * 384 + t], wh1 = g_whhT[j * 384 + 128 + t], wh2 = g_whhT[j * 384 + 256 + t];
#pragma unroll
        for (int q = 0; q < 16; q++) {
            float x = xs[q][j], h = hs[q][j];
            ir[q] += x * wi0; iz[q] += x * wi1; in_[q] += x * wi2;
            hr[q] += h * wh0; hz[q] += h * wh1; hn[q] += h * wh2;
        }
    }
#pragma unroll
    for (int q = 0; q < 16; q++) {
        float r = sigm(ir[q] + hr[q]);
        float z = sigm(iz[q] + hz[q]);
        float nn = tanhf(in_[q] + r * hn[q]);
        float hv = (1.0f - z) * nn + z * hs[q][t];
        g_h[(n0 + q) * Hd + t] = hv;
        if (out) out[(size_t)(n0 + q) * Hd + t] = hv;
    }
}

// ---------------- fused Set2Set step: LSTM + attend (4 graphs/block) ---------
__global__ void __launch_bounds__(128) k_s2s(const float* __restrict__ b_ih,
        const float* __restrict__ b_hh, const int* __restrict__ n2g,
        int last, float* __restrict__ out) {
    int g0 = blockIdx.x * 4;
    int t = threadIdx.x;
    int w = t >> 5, l = t & 31;
    __shared__ float qs[4][256];
    __shared__ float hsm[4][128];
    __shared__ int seg[5];
#pragma unroll
    for (int g = 0; g < 4; g++) {
        qs[g][t] = g_qs[(g0 + g) * 256 + t];
        qs[g][128 + t] = g_qs[(g0 + g) * 256 + 128 + t];
        hsm[g][t] = g_hs[(g0 + g) * Hd + t];
    }
    if (t < 5) {
        int target = g0 + t;
        int lo = 0, hi = Nn;
        while (lo < hi) { int m = (lo + hi) >> 1; if (n2g[m] < target) lo = m + 1; else hi = m; }
        seg[t] = lo;
    }
    __syncthreads();

    // ---- LSTM for 4 graphs ----
    float gi[4], gf[4], gg[4], go[4];
    {
        float bi = b_ih[t] + b_hh[t];
        float bf = b_ih[128 + t] + b_hh[128 + t];
        float bg = b_ih[256 + t] + b_hh[256 + t];
        float bo = b_ih[384 + t] + b_hh[384 + t];
#pragma unroll
        for (int g = 0; g < 4; g++) { gi[g] = bi; gf[g] = bf; gg[g] = bg; go[g] = bo; }
    }
    for (int j = 0; j < 256; j++) {
        const float* wi = &g_lihT[j * 512];
        float w0 = wi[t], w1 = wi[128 + t], w2 = wi[256 + t], w3 = wi[384 + t];
#pragma unroll
        for (int g = 0; g < 4; g++) {
            float q = qs[g][j];
            gi[g] += q * w0; gf[g] += q * w1; gg[g] += q * w2; go[g] += q * w3;
        }
    }
    for (int j = 0; j < Hd; j++) {
        const float* wh = &g_lhhT[j * 512];
        float w0 = wh[t], w1 = wh[128 + t], w2 = wh[256 + t], w3 = wh[384 + t];
#pragma unroll
        for (int g = 0; g < 4; g++) {
            float h = hsm[g][j];
            gi[g] += h * w0; gf[g] += h * w1; gg[g] += h * w2; go[g] += h * w3;
        }
    }
    __syncthreads();      // hsm reads done before overwrite
#pragma unroll
    for (int g = 0; g < 4; g++) {
        float c = sigm(gf[g]) * g_cs[(g0 + g) * Hd + t] + sigm(gi[g]) * tanhf(gg[g]);
        float h = sigm(go[g]) * tanhf(c);
        g_cs[(g0 + g) * Hd + t] = c;
        g_hs[(g0 + g) * Hd + t] = h;
        hsm[g][t] = h;
    }
    __syncthreads();

    // ---- attend: warp w handles graph g0+w (online segment softmax) ----
    {
        int b = g0 + w;
        int lo = seg[w], hi = seg[w + 1];
        float4 hv = *(float4*)&hsm[w][l * 4];
        float m = -INFINITY, s = 0.0f;
        float p0 = 0.0f, p1 = 0.0f, p2 = 0.0f, p3 = 0.0f;
        for (int i = lo; i < hi; i++) {
            float4 nf = *(const float4*)&g_h[(size_t)i * Hd + l * 4];
            float d = hv.x * nf.x + hv.y * nf.y + hv.z * nf.z + hv.w * nf.w;
#pragma unroll
            for (int o = 16; o; o >>= 1) d += __shfl_xor_sync(0xffffffffu, d, o);
            float mn = fmaxf(m, d);
            float corr = expf(m - mn);     // exp(-inf) = 0 first iter
            float wg = expf(d - mn);
            s = s * corr + wg;
            p0 = p0 * corr + wg * nf.x; p1 = p1 * corr + wg * nf.y;
            p2 = p2 * corr + wg * nf.z; p3 = p3 * corr + wg * nf.w;
            m = mn;
        }
        float inv = (s > 0.0f) ? 1.0f / s : 0.0f;
        float4 pooled = make_float4(p0 * inv, p1 * inv, p2 * inv, p3 * inv);
        *(float4*)&g_qs[b * 256 + l * 4] = hv;
        *(float4*)&g_qs[b * 256 + 128 + l * 4] = pooled;
        if (last) {
            *(float4*)&out[b * 256 + l * 4] = hv;
            *(float4*)&out[b * 256 + 128 + l * 4] = pooled;
        }
    }
}

extern "C" void kernel_launch(void* const* d_in, const int* in_sizes, int n_in,
                              void* d_out, int out_size) {
    const int*   unit_type    = (const int*)d_in[0];
    const int*   node_in      = (const int*)d_in[1];
    const int*   node_out     = (const int*)d_in[2];
    const int*   node2graph   = (const int*)d_in[3];
    const float* edge_feature = (const float*)d_in[4];
    const float* embedding    = (const float*)d_in[5];
    const float* mlp_w1       = (const float*)d_in[6];
    const float* mlp_b1       = (const float*)d_in[7];
    const float* mlp_w2       = (const float*)d_in[8];
    const float* mlp_b2       = (const float*)d_in[9];
    const float* gru_w_ih     = (const float*)d_in[10];
    const float* gru_w_hh     = (const float*)d_in[11];
    const float* gru_b_ih     = (const float*)d_in[12];
    const float* gru_b_hh     = (const float*)d_in[13];
    const float* lstm_w_ih    = (const float*)d_in[14];
    const float* lstm_w_hh    = (const float*)d_in[15];
    const float* lstm_b_ih    = (const float*)d_in[16];
    const float* lstm_b_hh    = (const float*)d_in[17];
    float* out = (float*)d_out;

    cudaFuncSetAttribute(k_gemm_mma, cudaFuncAttributeMaxDynamicSharedMemorySize, SMEM_GEMM);

    k_init_h<<<Nn, Hd>>>(unit_type, embedding);
    k_prep<<<8128, 256>>>(mlp_w2, gru_w_ih, gru_w_hh, lstm_w_ih, lstm_w_hh);
    k_edge_hidden<<<Ee, Hd>>>(edge_feature, mlp_w1, mlp_b1);
    // GEMM + fused layer-1 message (g_upd pre-zeroed by k_prep)
    k_gemm_mma<<<dim3(64, 128), 512, SMEM_GEMM>>>(mlp_b2, node_in, node_out);
    k_gru<<<Nn / 16, Hd>>>(gru_b_ih, gru_b_hh, nullptr);

    for (int l = 1; l < 3; l++) {
        k_message<<<Ee, Hd>>>(node_in, node_out);
        // last GRU writes node_feature directly into the output
        k_gru<<<Nn / 16, Hd>>>(gru_b_ih, gru_b_hh, (l == 2) ? out + Bg * 256 : nullptr);
    }

    for (int s = 0; s < 3; s++) {
        k_s2s<<<Bg / 4, 128>>>(lstm_b_ih, lstm_b_hh, node2graph, s == 2, out);
    }
}

// round 15
// speedup vs baseline: 1.4474x; 1.0460x over previous
#include <cuda_runtime.h>
#include <cuda_bf16.h>
#include <cuda_fp16.h>
#include <cstdint>
#include <math.h>

// Problem constants
#define Hd   128
#define Bg   512
#define Nn   8192
#define Ee   16384
#define EDIM 32

// ---------------- scratch (device globals; no allocation) ----------------
__device__ __half g_transform[268435456];  // [E, H*H] fp16 = 512 MiB
__device__ __half g_hmid[Ee * Hd];         // fp16 edge hidden
__device__ __half g_w2T[16384 * 128];      // [N, K] = W2 transposed, fp16
__device__ float g_h[Nn * Hd];             // layer_input / hx  [N, 128]
__device__ float g_upd[Nn * Hd];           // scatter target     [N, 128]
__device__ float g_wihT[Hd * 384];         // gru w_ih transposed [j][t]
__device__ float g_whhT[Hd * 384];
__device__ float g_lihT[256 * 512];        // lstm w_ih transposed [j][t]
__device__ float g_lhhT[Hd * 512];
__device__ float g_hs[Bg * Hd];            // set2set h
__device__ float g_cs[Bg * Hd];            // set2set c
__device__ float g_qs[Bg * 256];           // q_star

__device__ __forceinline__ float sigm(float x) { return 1.0f / (1.0f + expf(-x)); }

__device__ __forceinline__ uint32_t smem_u32(const void* p) {
    uint32_t a;
    asm("{ .reg .u64 t; cvta.to.shared.u64 t, %1; cvt.u32.u64 %0, t; }" : "=r"(a) : "l"(p));
    return a;
}

#define LDSM_X4(r, a) \
    asm volatile("ldmatrix.sync.aligned.m8n8.x4.shared.b16 {%0,%1,%2,%3}, [%4];" \
        : "=r"((r)[0]), "=r"((r)[1]), "=r"((r)[2]), "=r"((r)[3]) : "r"(a))

__device__ __forceinline__ void mma16816h(float* c, const uint32_t* a, uint32_t b0, uint32_t b1) {
    asm volatile("mma.sync.aligned.m16n8k16.row.col.f32.f16.f16.f32 "
        "{%0,%1,%2,%3}, {%4,%5,%6,%7}, {%8,%9}, {%0,%1,%2,%3};"
        : "+f"(c[0]), "+f"(c[1]), "+f"(c[2]), "+f"(c[3])
        : "r"(a[0]), "r"(a[1]), "r"(a[2]), "r"(a[3]), "r"(b0), "r"(b1));
}

#define CP_ASYNC16(dst, src) \
    asm volatile("cp.async.cg.shared.global [%0], [%1], 16;" :: "r"(dst), "l"(src) : "memory")
#define CP_COMMIT() asm volatile("cp.async.commit_group;" ::: "memory")
#define CP_WAIT(n)  asm volatile("cp.async.wait_group %0;" :: "n"(n) : "memory")

// ---------------- init: node embedding gather ----------------
__global__ void k_init_h(const int* __restrict__ ut, const float* __restrict__ emb) {
    int n = blockIdx.x, t = threadIdx.x;
    g_h[n * Hd + t] = emb[ut[n] * Hd + t];
}

// ---------------- prep: W2 transpose (fp16) + weight transposes + zeroing ----
__global__ void __launch_bounds__(256) k_prep(const float* __restrict__ w2,
        const float* __restrict__ gih, const float* __restrict__ ghh,
        const float* __restrict__ lih, const float* __restrict__ lhh) {
    int bid = blockIdx.x, tid = threadIdx.x;
    if (bid < 2048) {
        __shared__ float ts[32][33];
        int kt = (bid & 3) * 32, nt = (bid >> 2) * 32;
        int r = tid >> 3, c4 = (tid & 7) * 4;
        const float4 v = *(const float4*)&w2[(size_t)(kt + r) * 16384 + nt + c4];
        ts[r][c4] = v.x; ts[r][c4 + 1] = v.y; ts[r][c4 + 2] = v.z; ts[r][c4 + 3] = v.w;
        __syncthreads();
        int n = nt + r;
        __half h4[4];
#pragma unroll
        for (int q = 0; q < 4; q++) h4[q] = __float2half(ts[c4 + q][r]);
        *(uint2*)&g_w2T[(size_t)n * 128 + kt + c4] = *(uint2*)h4;
        return;
    }
    long i = (long)(bid - 2048) * 256 + tid;
    if (i < 49152) { int t = i / 128, j = i % 128; g_wihT[j * 384 + t] = gih[i]; g_whhT[j * 384 + t] = ghh[i]; return; }
    i -= 49152;
    if (i < 131072) { int t = i / 256, j = i % 256; g_lihT[j * 512 + t] = lih[i]; return; }
    i -= 131072;
    if (i < 65536) { int t = i / 128, j = i % 128; g_lhhT[j * 512 + t] = lhh[i]; return; }
    i -= 65536;
    if (i < Nn * Hd) { g_upd[i] = 0.0f; return; }
    i -= Nn * Hd;
    if (i < Bg * Hd) { g_hs[i] = 0.0f; return; }
    i -= Bg * Hd;
    if (i < Bg * Hd) { g_cs[i] = 0.0f; return; }
    i -= Bg * Hd;
    if (i < Bg * 256) { g_qs[i] = 0.0f; return; }
}

// ---------------- edge hidden: hmid = relu(ef @ W1 + b1) -> fp16 -------------
__global__ void k_edge_hidden(const float* __restrict__ ef, const float* __restrict__ w1,
                              const float* __restrict__ b1) {
    int e = blockIdx.x, t = threadIdx.x;
    __shared__ float efs[EDIM];
    if (t < EDIM) efs[t] = ef[e * EDIM + t];
    __syncthreads();
    float acc = b1[t];
#pragma unroll
    for (int k = 0; k < EDIM; k++) acc += efs[k] * w1[k * Hd + t];
    g_hmid[e * Hd + t] = __float2half(fmaxf(acc, 0.0f));
}

// ---------------- cp.async-pipelined fp16 mma GEMM + fused layer-1 message --
// Block 64(edges) x 256(cols). 8 warps 2x4, warp tile 32x64, 256 threads.
// 2 stages x 40 KB {A 8K | B 32K} -> ~83 KB SMEM -> 2 CTAs/SM.
// x-gather cp.async'd into retired stage0 after chunk0 (R10 pattern).
#define STAGE 40960
#define SB_B  8192
#define OFF_MSG 81920
#define OFF_IDX 82432
#define SMEM_GEMM 82688
__global__ void __launch_bounds__(256, 2) k_gemm_mma(const float* __restrict__ bias,
        const int* __restrict__ node_in, const int* __restrict__ node_out) {
    extern __shared__ char sm[];
    const int tid = threadIdx.x;
    const int wid = tid >> 5, l = tid & 31;
    const int wm = wid & 1, wn = wid >> 1;            // 2 x 4 warp grid
    const int rowBase = blockIdx.y * 64;
    const int colBase = blockIdx.x * 256;
    const uint32_t smB = smem_u32(sm);
    int* idx = (int*)(sm + OFF_IDX);

    // issue both K-chunk stages (groups 0, 1)
#pragma unroll
    for (int s = 0; s < 2; s++) {
        const uint32_t sb = smB + s * STAGE;
        const int kOff = s * 64;
#pragma unroll
        for (int i0 = 0; i0 < 512; i0 += 256) {
            int i = i0 + tid;
            int r = i >> 3, kk = i & 7;
            uint32_t off = ((uint32_t)r << 7) + ((uint32_t)kk << 4);
            off ^= (r & 7) << 4;
            CP_ASYNC16(sb + off, &g_hmid[(size_t)(rowBase + r) * 128 + kOff + kk * 8]);
        }
#pragma unroll
        for (int i0 = 0; i0 < 2048; i0 += 256) {
            int i = i0 + tid;
            int r = i >> 3, kk = i & 7;
            uint32_t off = ((uint32_t)r << 7) + ((uint32_t)kk << 4);
            off ^= (r & 7) << 4;
            CP_ASYNC16(sb + SB_B + off, &g_w2T[(size_t)(colBase + r) * 128 + kOff + kk * 8]);
        }
        CP_COMMIT();
    }
    if (tid < 64) idx[tid] = node_in[rowBase + tid];
    if (tid >= 128 && tid < 256) ((float*)(sm + OFF_MSG))[tid - 128] = 0.0f;

    float acc[2][8][4];
#pragma unroll
    for (int mf = 0; mf < 2; mf++)
#pragma unroll
        for (int nf = 0; nf < 8; nf++)
#pragma unroll
            for (int q = 0; q < 4; q++) acc[mf][nf][q] = 0.0f;

    const int rA = l & 15;
    const int ksA = (l >> 4) & 1;
    const int nAdd = (l & 7) + ((l >> 4) << 3);
    const int kAdd = ((l >> 3) & 1) << 3;

#define DO_CHUNK(SB)                                                              \
    _Pragma("unroll")                                                             \
    for (int ks = 0; ks < 4; ks++) {                                              \
        const int k0 = ks * 16;                                                   \
        uint32_t ra[2][4];                                                        \
        _Pragma("unroll")                                                         \
        for (int mf = 0; mf < 2; mf++) {                                          \
            int r = wm * 32 + mf * 16 + rA;                                       \
            uint32_t off = ((uint32_t)r << 7) + (uint32_t)((k0 + ksA * 8) << 1);  \
            off ^= (r & 7) << 4;                                                  \
            LDSM_X4(ra[mf], (SB) + off);                                          \
        }                                                                         \
        _Pragma("unroll")                                                         \
        for (int q = 0; q < 4; q++) {                                             \
            uint32_t rb[4];                                                       \
            int n = wn * 64 + q * 16 + nAdd;                                      \
            uint32_t off = ((uint32_t)n << 7) + (uint32_t)((k0 + kAdd) << 1);     \
            off ^= (n & 7) << 4;                                                  \
            LDSM_X4(rb, (SB) + SB_B + off);                                       \
            _Pragma("unroll")                                                     \
            for (int mf = 0; mf < 2; mf++) {                                      \
                mma16816h(acc[mf][2 * q],     ra[mf], rb[0], rb[1]);              \
                mma16816h(acc[mf][2 * q + 1], ra[mf], rb[2], rb[3]);              \
            }                                                                     \
        }                                                                         \
    }

    CP_WAIT(1);
    __syncthreads();            // stage0 ready; idx visible
    DO_CHUNK(smB);              // chunk 0
    CP_WAIT(0);
    __syncthreads();            // stage1 ready; stage0 retired
    // prefetch x-gather (64 rows x 128 fp32 = 32 KB) into retired stage0
    {
#pragma unroll
        for (int i0 = 0; i0 < 2048; i0 += 256) {
            int i = i0 + tid;
            int r = i >> 5, seg = i & 31;
            CP_ASYNC16(smB + (uint32_t)(r * 512 + seg * 16),
                       &g_h[(size_t)idx[r] * 128 + seg * 4]);
        }
        CP_COMMIT();
    }
    DO_CHUNK(smB + STAGE);      // chunk 1
#undef DO_CHUNK
    CP_WAIT(0);
    __syncthreads();            // xs ready

    // ---- epilogue: bias add + fp16 streaming store + fused message ----
    float* xs = (float*)sm;                // [64][128] fp32 (over stage0)
    float* smsg = (float*)(sm + OFF_MSG);  // [2][64]
    const int il = wn >> 1;                // this warp's i within the pair
#pragma unroll
    for (int mf = 0; mf < 2; mf++) {
        int r0 = wm * 32 + mf * 16 + (l >> 2);
        int row = rowBase + r0;
        float p0 = 0.0f, p1 = 0.0f;
#pragma unroll
        for (int nf = 0; nf < 8; nf++) {
            int cl = wn * 64 + nf * 8 + (l & 3) * 2;
            int col = colBase + cl;
            int jl = cl & 127;
            float b0 = bias[col], b1 = bias[col + 1];
            float t00 = acc[mf][nf][0] + b0, t01 = acc[mf][nf][1] + b1;
            float t10 = acc[mf][nf][2] + b0, t11 = acc[mf][nf][3] + b1;
            __half2 h0 = __floats2half2_rn(t00, t01);
            __half2 h1 = __floats2half2_rn(t10, t11);
            __stcs((uint32_t*)&g_transform[(size_t)row * 16384 + col], *(uint32_t*)&h0);
            __stcs((uint32_t*)&g_transform[(size_t)(row + 8) * 16384 + col], *(uint32_t*)&h1);
            p0 += t00 * xs[r0 * 128 + jl] + t01 * xs[r0 * 128 + jl + 1];
            p1 += t10 * xs[(r0 + 8) * 128 + jl] + t11 * xs[(r0 + 8) * 128 + jl + 1];
        }
        p0 += __shfl_xor_sync(0xffffffffu, p0, 1);
        p0 += __shfl_xor_sync(0xffffffffu, p0, 2);
        p1 += __shfl_xor_sync(0xffffffffu, p1, 1);
        p1 += __shfl_xor_sync(0xffffffffu, p1, 2);
        if ((l & 3) == 0) {
            atomicAdd(&smsg[il * 64 + r0], p0);
            atomicAdd(&smsg[il * 64 + r0 + 8], p1);
        }
    }
    __syncthreads();
    if (tid < 128) {
        int r = tid & 63, ii = tid >> 6;
        int dst = node_out[rowBase + r];
        atomicAdd(&g_upd[(size_t)dst * 128 + 2 * blockIdx.x + ii], smsg[ii * 64 + r]);
    }
}

// ---------------- message (layers 2,3): warp-per-row matvec, fp16 transform --
__global__ void k_message(const int* __restrict__ node_in, const int* __restrict__ node_out) {
    int e = blockIdx.x, t = threadIdx.x;
    __shared__ float v[Hd];
    int src = node_in[e];
    v[t] = g_h[src * Hd + t];
    __syncthreads();
    int lane = t & 31, w = t >> 5;
    int dst = node_out[e];
    const __half* T = &g_transform[(size_t)e * 16384];
    float v0 = v[lane * 4 + 0], v1 = v[lane * 4 + 1], v2 = v[lane * 4 + 2], v3 = v[lane * 4 + 3];
#pragma unroll
    for (int r = w; r < Hd; r += 4) {
        uint2 raw = __ldcs((const uint2*)&T[r * 128 + lane * 4]);
        float2 a = __half22float2(*(__half2*)&raw.x);
        float2 b = __half22float2(*(__half2*)&raw.y);
        float s = a.x * v0 + a.y * v1 + b.x * v2 + b.y * v3;
#pragma unroll
        for (int o = 16; o; o >>= 1) s += __shfl_down_sync(0xffffffffu, s, o);
        if (lane == 0) atomicAdd(&g_upd[dst * Hd + r], s);
    }
}

// ---------------- GRU: 16 nodes per block; re-zeroes g_upd -------------------
__global__ void __launch_bounds__(128) k_gru(const float* __restrict__ b_ih,
                                             const float* __restrict__ b_hh,
                                             float* __restrict__ out) {
    int n0 = blockIdx.x * 16;
    int t = threadIdx.x;
    __shared__ float xs[16][Hd];
    __shared__ float hs[16][Hd];
#pragma unroll
    for (int q = 0; q < 16; q++) {
        xs[q][t] = fmaxf(g_upd[(n0 + q) * Hd + t], 0.0f);
        g_upd[(n0 + q) * Hd + t] = 0.0f;
        hs[q][t] = g_h[(n0 + q) * Hd + t];
    }
    __syncthreads();
    float ir[16], iz[16], in_[16], hr[16], hz[16], hn[16];
    float bir = b_ih[t], biz = b_ih[128 + t], bin = b_ih[256 + t];
    float bhr = b_hh[t], bhz = b_hh[128 + t], bhn = b_hh[256 + t];
#pragma unroll
    for (int q = 0; q < 16; q++) { ir[q] = bir; iz[q] = biz; in_[q] = bin; hr[q] = bhr; hz[q] = bhz; hn[q] = bhn; }
    for (int j = 0; j < Hd; j++) {
        float wi0 = g_wihT[j * 384 + t], wi1 = g_wihT[j * 384 + 128 + t], wi2 = g_wihT[j * 384 + 256 + t];
        float wh0 = g_whhT[j * 384 + t], wh1 = g_whhT[j * 384 + 128 + t], wh2 = g_whhT[j * 384 + 256 + t];
#pragma unroll
        for (int q = 0; q < 16; q++) {
            float x = xs[q][j], h = hs[q][j];
            ir[q] += x * wi0; iz[q] += x * wi1; in_[q] += x * wi2;
            hr[q] += h * wh0; hz[q] += h * wh1; hn[q] += h * wh2;
        }
    }
#pragma unroll
    for (int q = 0; q < 16; q++) {
        float r = sigm(ir[q] + hr[q]);
        float z = sigm(iz[q] + hz[q]);
        float nn = tanhf(in_[q] + r * hn[q]);
        float hv = (1.0f - z) * nn + z * hs[q][t];
        g_h[(n0 + q) * Hd + t] = hv;
        if (out) out[(size_t)(n0 + q) * Hd + t] = hv;
    }
}

// ---------------- fused Set2Set step: LSTM + attend (4 graphs/block) ---------
__global__ void __launch_bounds__(128) k_s2s(const float* __restrict__ b_ih,
        const float* __restrict__ b_hh, const int* __restrict__ n2g,
        int last, float* __restrict__ out) {
    int g0 = blockIdx.x * 4;
    int t = threadIdx.x;
    int w = t >> 5, l = t & 31;
    __shared__ float qs[4][256];
    __shared__ float hsm[4][128];
    __shared__ int seg[5];
#pragma unroll
    for (int g = 0; g < 4; g++) {
        qs[g][t] = g_qs[(g0 + g) * 256 + t];
        qs[g][128 + t] = g_qs[(g0 + g) * 256 + 128 + t];
        hsm[g][t] = g_hs[(g0 + g) * Hd + t];
    }
    if (t < 5) {
        int target = g0 + t;
        int lo = 0, hi = Nn;
        while (lo < hi) { int m = (lo + hi) >> 1; if (n2g[m] < target) lo = m + 1; else hi = m; }
        seg[t] = lo;
    }
    __syncthreads();

    // ---- LSTM for 4 graphs ----
    float gi[4], gf[4], gg[4], go[4];
    {
        float bi = b_ih[t] + b_hh[t];
        float bf = b_ih[128 + t] + b_hh[128 + t];
        float bg = b_ih[256 + t] + b_hh[256 + t];
        float bo = b_ih[384 + t] + b_hh[384 + t];
#pragma unroll
        for (int g = 0; g < 4; g++) { gi[g] = bi; gf[g] = bf; gg[g] = bg; go[g] = bo; }
    }
    for (int j = 0; j < 256; j++) {
        const float* wi = &g_lihT[j * 512];
        float w0 = wi[t], w1 = wi[128 + t], w2 = wi[256 + t], w3 = wi[384 + t];
#pragma unroll
        for (int g = 0; g < 4; g++) {
            float q = qs[g][j];
            gi[g] += q * w0; gf[g] += q * w1; gg[g] += q * w2; go[g] += q * w3;
        }
    }
    for (int j = 0; j < Hd; j++) {
        const float* wh = &g_lhhT[j * 512];
        float w0 = wh[t], w1 = wh[128 + t], w2 = wh[256 + t], w3 = wh[384 + t];
#pragma unroll
        for (int g = 0; g < 4; g++) {
            float h = hsm[g][j];
            gi[g] += h * w0; gf[g] += h * w1; gg[g] += h * w2; go[g] += h * w3;
        }
    }
    __syncthreads();      // hsm reads done before overwrite
#pragma unroll
    for (int g = 0; g < 4; g++) {
        float c = sigm(gf[g]) * g_cs[(g0 + g) * Hd + t] + sigm(gi[g]) * tanhf(gg[g]);
        float h = sigm(go[g]) * tanhf(c);
        g_cs[(g0 + g) * Hd + t] = c;
        g_hs[(g0 + g) * Hd + t] = h;
        hsm[g][t] = h;
    }
    __syncthreads();

    // ---- attend: warp w handles graph g0+w (online segment softmax) ----
    {
        int b = g0 + w;
        int lo = seg[w], hi = seg[w + 1];
        float4 hv = *(float4*)&hsm[w][l * 4];
        float m = -INFINITY, s = 0.0f;
        float p0 = 0.0f, p1 = 0.0f, p2 = 0.0f, p3 = 0.0f;
        for (int i = lo; i < hi; i++) {
            float4 nf = *(const float4*)&g_h[(size_t)i * Hd + l * 4];
            float d = hv.x * nf.x + hv.y * nf.y + hv.z * nf.z + hv.w * nf.w;
#pragma unroll
            for (int o = 16; o; o >>= 1) d += __shfl_xor_sync(0xffffffffu, d, o);
            float mn = fmaxf(m, d);
            float corr = expf(m - mn);     // exp(-inf) = 0 first iter
            float wg = expf(d - mn);
            s = s * corr + wg;
            p0 = p0 * corr + wg * nf.x; p1 = p1 * corr + wg * nf.y;
            p2 = p2 * corr + wg * nf.z; p3 = p3 * corr + wg * nf.w;
            m = mn;
        }
        float inv = (s > 0.0f) ? 1.0f / s : 0.0f;
        float4 pooled = make_float4(p0 * inv, p1 * inv, p2 * inv, p3 * inv);
        *(float4*)&g_qs[b * 256 + l * 4] = hv;
        *(float4*)&g_qs[b * 256 + 128 + l * 4] = pooled;
        if (last) {
            *(float4*)&out[b * 256 + l * 4] = hv;
            *(float4*)&out[b * 256 + 128 + l * 4] = pooled;
        }
    }
}

extern "C" void kernel_launch(void* const* d_in, const int* in_sizes, int n_in,
                              void* d_out, int out_size) {
    const int*   unit_type    = (const int*)d_in[0];
    const int*   node_in      = (const int*)d_in[1];
    const int*   node_out     = (const int*)d_in[2];
    const int*   node2graph   = (const int*)d_in[3];
    const float* edge_feature = (const float*)d_in[4];
    const float* embedding    = (const float*)d_in[5];
    const float* mlp_w1       = (const float*)d_in[6];
    const float* mlp_b1       = (const float*)d_in[7];
    const float* mlp_w2       = (const float*)d_in[8];
    const float* mlp_b2       = (const float*)d_in[9];
    const float* gru_w_ih     = (const float*)d_in[10];
    const float* gru_w_hh     = (const float*)d_in[11];
    const float* gru_b_ih     = (const float*)d_in[12];
    const float* gru_b_hh     = (const float*)d_in[13];
    const float* lstm_w_ih    = (const float*)d_in[14];
    const float* lstm_w_hh    = (const float*)d_in[15];
    const float* lstm_b_ih    = (const float*)d_in[16];
    const float* lstm_b_hh    = (const float*)d_in[17];
    float* out = (float*)d_out;

    cudaFuncSetAttribute(k_gemm_mma, cudaFuncAttributeMaxDynamicSharedMemorySize, SMEM_GEMM);

    k_init_h<<<Nn, Hd>>>(unit_type, embedding);
    k_prep<<<8128, 256>>>(mlp_w2, gru_w_ih, gru_w_hh, lstm_w_ih, lstm_w_hh);
    k_edge_hidden<<<Ee, Hd>>>(edge_feature, mlp_w1, mlp_b1);
    // GEMM + fused layer-1 message (g_upd pre-zeroed by k_prep)
    k_gemm_mma<<<dim3(64, 256), 256, SMEM_GEMM>>>(mlp_b2, node_in, node_out);
    k_gru<<<Nn / 16, Hd>>>(gru_b_ih, gru_b_hh, nullptr);

    for (int l = 1; l < 3; l++) {
        k_message<<<Ee, Hd>>>(node_in, node_out);
        // last GRU writes node_feature directly into the output
        k_gru<<<Nn / 16, Hd>>>(gru_b_ih, gru_b_hh, (l == 2) ? out + Bg * 256 : nullptr);
    }

    for (int s = 0; s < 3; s++) {
        k_s2s<<<Bg / 4, 128>>>(lstm_b_ih, lstm_b_hh, node2graph, s == 2, out);
    }
}

// round 16
// speedup vs baseline: 1.4689x; 1.0149x over previous
#include <cuda_runtime.h>
#include <cuda_bf16.h>
#include <cuda_fp16.h>
#include <cstdint>
#include <math.h>

// Problem constants
#define Hd   128
#define Bg   512
#define Nn   8192
#define Ee   16384
#define EDIM 32

// ---------------- scratch (device globals; no allocation) ----------------
__device__ __half g_transform[268435456];  // [E, H*H] fp16 = 512 MiB
__device__ __half g_hmid[Ee * Hd];         // fp16 edge hidden
__device__ __half g_w2T[16384 * 128];      // [N, K] = W2 transposed, fp16
__device__ float g_h[Nn * Hd];             // layer_input / hx  [N, 128]
__device__ float g_upd[Nn * Hd];           // scatter target     [N, 128]
__device__ float g_wihT[Hd * 384];         // gru w_ih transposed [j][t]
__device__ float g_whhT[Hd * 384];
__device__ float g_lihT[256 * 512];        // lstm w_ih transposed [j][t]
__device__ float g_lhhT[Hd * 512];
__device__ float g_hs[Bg * Hd];            // set2set h
__device__ float g_cs[Bg * Hd];            // set2set c
__device__ float g_qs[Bg * 256];           // q_star

__device__ __forceinline__ float sigm(float x) { return 1.0f / (1.0f + expf(-x)); }

__device__ __forceinline__ uint32_t smem_u32(const void* p) {
    uint32_t a;
    asm("{ .reg .u64 t; cvta.to.shared.u64 t, %1; cvt.u32.u64 %0, t; }" : "=r"(a) : "l"(p));
    return a;
}

#define LDSM_X4(r, a) \
    asm volatile("ldmatrix.sync.aligned.m8n8.x4.shared.b16 {%0,%1,%2,%3}, [%4];" \
        : "=r"((r)[0]), "=r"((r)[1]), "=r"((r)[2]), "=r"((r)[3]) : "r"(a))

__device__ __forceinline__ void mma16816h(float* c, const uint32_t* a, uint32_t b0, uint32_t b1) {
    asm volatile("mma.sync.aligned.m16n8k16.row.col.f32.f16.f16.f32 "
        "{%0,%1,%2,%3}, {%4,%5,%6,%7}, {%8,%9}, {%0,%1,%2,%3};"
        : "+f"(c[0]), "+f"(c[1]), "+f"(c[2]), "+f"(c[3])
        : "r"(a[0]), "r"(a[1]), "r"(a[2]), "r"(a[3]), "r"(b0), "r"(b1));
}

#define CP_ASYNC16(dst, src) \
    asm volatile("cp.async.cg.shared.global [%0], [%1], 16;" :: "r"(dst), "l"(src) : "memory")
#define CP_COMMIT() asm volatile("cp.async.commit_group;" ::: "memory")
#define CP_WAIT(n)  asm volatile("cp.async.wait_group %0;" :: "n"(n) : "memory")

// ---------------- init: node embedding gather ----------------
__global__ void k_init_h(const int* __restrict__ ut, const float* __restrict__ emb) {
    int n = blockIdx.x, t = threadIdx.x;
    g_h[n * Hd + t] = emb[ut[n] * Hd + t];
}

// ---------------- prep: W2 transpose (fp16) + weight transposes + zeroing ----
__global__ void __launch_bounds__(256) k_prep(const float* __restrict__ w2,
        const float* __restrict__ gih, const float* __restrict__ ghh,
        const float* __restrict__ lih, const float* __restrict__ lhh) {
    int bid = blockIdx.x, tid = threadIdx.x;
    if (bid < 2048) {
        __shared__ float ts[32][33];
        int kt = (bid & 3) * 32, nt = (bid >> 2) * 32;
        int r = tid >> 3, c4 = (tid & 7) * 4;
        const float4 v = *(const float4*)&w2[(size_t)(kt + r) * 16384 + nt + c4];
        ts[r][c4] = v.x; ts[r][c4 + 1] = v.y; ts[r][c4 + 2] = v.z; ts[r][c4 + 3] = v.w;
        __syncthreads();
        int n = nt + r;
        __half h4[4];
#pragma unroll
        for (int q = 0; q < 4; q++) h4[q] = __float2half(ts[c4 + q][r]);
        *(uint2*)&g_w2T[(size_t)n * 128 + kt + c4] = *(uint2*)h4;
        return;
    }
    long i = (long)(bid - 2048) * 256 + tid;
    if (i < 49152) { int t = i / 128, j = i % 128; g_wihT[j * 384 + t] = gih[i]; g_whhT[j * 384 + t] = ghh[i]; return; }
    i -= 49152;
    if (i < 131072) { int t = i / 256, j = i % 256; g_lihT[j * 512 + t] = lih[i]; return; }
    i -= 131072;
    if (i < 65536) { int t = i / 128, j = i % 128; g_lhhT[j * 512 + t] = lhh[i]; return; }
    i -= 65536;
    if (i < Nn * Hd) { g_upd[i] = 0.0f; return; }
    i -= Nn * Hd;
    if (i < Bg * Hd) { g_hs[i] = 0.0f; return; }
    i -= Bg * Hd;
    if (i < Bg * Hd) { g_cs[i] = 0.0f; return; }
    i -= Bg * Hd;
    if (i < Bg * 256) { g_qs[i] = 0.0f; return; }
}

// ---------------- edge hidden: hmid = relu(ef @ W1 + b1) -> fp16 -------------
__global__ void k_edge_hidden(const float* __restrict__ ef, const float* __restrict__ w1,
                              const float* __restrict__ b1) {
    int e = blockIdx.x, t = threadIdx.x;
    __shared__ float efs[EDIM];
    if (t < EDIM) efs[t] = ef[e * EDIM + t];
    __syncthreads();
    float acc = b1[t];
#pragma unroll
    for (int k = 0; k < EDIM; k++) acc += efs[k] * w1[k * Hd + t];
    g_hmid[e * Hd + t] = __float2half(fmaxf(acc, 0.0f));
}

// ---------------- cp.async-pipelined fp16 mma GEMM + fused layer-1 message --
// Block 64(edges) x 256(cols). 8 warps 2x4, warp tile 32x64, 256 threads.
// 2 stages x 40 KB {A 8K | B 32K} -> ~83 KB SMEM -> 2 CTAs/SM.
// Output tile staged into retired stage1 SMEM, written with dense 16B stores.
#define STAGE 40960
#define SB_B  8192
#define OFF_MSG 81920
#define OFF_IDX 82432
#define SMEM_GEMM 82688
__global__ void __launch_bounds__(256, 2) k_gemm_mma(const float* __restrict__ bias,
        const int* __restrict__ node_in, const int* __restrict__ node_out) {
    extern __shared__ char sm[];
    const int tid = threadIdx.x;
    const int wid = tid >> 5, l = tid & 31;
    const int wm = wid & 1, wn = wid >> 1;            // 2 x 4 warp grid
    const int rowBase = blockIdx.y * 64;
    const int colBase = blockIdx.x * 256;
    const uint32_t smB = smem_u32(sm);
    int* idx = (int*)(sm + OFF_IDX);

    // issue both K-chunk stages (groups 0, 1)
#pragma unroll
    for (int s = 0; s < 2; s++) {
        const uint32_t sb = smB + s * STAGE;
        const int kOff = s * 64;
#pragma unroll
        for (int i0 = 0; i0 < 512; i0 += 256) {
            int i = i0 + tid;
            int r = i >> 3, kk = i & 7;
            uint32_t off = ((uint32_t)r << 7) + ((uint32_t)kk << 4);
            off ^= (r & 7) << 4;
            CP_ASYNC16(sb + off, &g_hmid[(size_t)(rowBase + r) * 128 + kOff + kk * 8]);
        }
#pragma unroll
        for (int i0 = 0; i0 < 2048; i0 += 256) {
            int i = i0 + tid;
            int r = i >> 3, kk = i & 7;
            uint32_t off = ((uint32_t)r << 7) + ((uint32_t)kk << 4);
            off ^= (r & 7) << 4;
            CP_ASYNC16(sb + SB_B + off, &g_w2T[(size_t)(colBase + r) * 128 + kOff + kk * 8]);
        }
        CP_COMMIT();
    }
    if (tid < 64) idx[tid] = node_in[rowBase + tid];
    if (tid >= 128 && tid < 256) ((float*)(sm + OFF_MSG))[tid - 128] = 0.0f;

    float acc[2][8][4];
#pragma unroll
    for (int mf = 0; mf < 2; mf++)
#pragma unroll
        for (int nf = 0; nf < 8; nf++)
#pragma unroll
            for (int q = 0; q < 4; q++) acc[mf][nf][q] = 0.0f;

    const int rA = l & 15;
    const int ksA = (l >> 4) & 1;
    const int nAdd = (l & 7) + ((l >> 4) << 3);
    const int kAdd = ((l >> 3) & 1) << 3;

#define DO_CHUNK(SB)                                                              \
    _Pragma("unroll")                                                             \
    for (int ks = 0; ks < 4; ks++) {                                              \
        const int k0 = ks * 16;                                                   \
        uint32_t ra[2][4];                                                        \
        _Pragma("unroll")                                                         \
        for (int mf = 0; mf < 2; mf++) {                                          \
            int r = wm * 32 + mf * 16 + rA;                                       \
            uint32_t off = ((uint32_t)r << 7) + (uint32_t)((k0 + ksA * 8) << 1);  \
            off ^= (r & 7) << 4;                                                  \
            LDSM_X4(ra[mf], (SB) + off);                                          \
        }                                                                         \
        _Pragma("unroll")                                                         \
        for (int q = 0; q < 4; q++) {                                             \
            uint32_t rb[4];                                                       \
            int n = wn * 64 + q * 16 + nAdd;                                      \
            uint32_t off = ((uint32_t)n << 7) + (uint32_t)((k0 + kAdd) << 1);     \
            off ^= (n & 7) << 4;                                                  \
            LDSM_X4(rb, (SB) + SB_B + off);                                       \
            _Pragma("unroll")                                                     \
            for (int mf = 0; mf < 2; mf++) {                                      \
                mma16816h(acc[mf][2 * q],     ra[mf], rb[0], rb[1]);              \
                mma16816h(acc[mf][2 * q + 1], ra[mf], rb[2], rb[3]);              \
            }                                                                     \
        }                                                                         \
    }

    CP_WAIT(1);
    __syncthreads();            // stage0 ready; idx visible
    DO_CHUNK(smB);              // chunk 0
    CP_WAIT(0);
    __syncthreads();            // stage1 ready; stage0 retired
    // prefetch x-gather (64 rows x 128 fp32 = 32 KB) into retired stage0
    {
#pragma unroll
        for (int i0 = 0; i0 < 2048; i0 += 256) {
            int i = i0 + tid;
            int r = i >> 5, seg = i & 31;
            CP_ASYNC16(smB + (uint32_t)(r * 512 + seg * 16),
                       &g_h[(size_t)idx[r] * 128 + seg * 4]);
        }
        CP_COMMIT();
    }
    DO_CHUNK(smB + STAGE);      // chunk 1
#undef DO_CHUNK
    CP_WAIT(0);
    __syncthreads();            // xs ready; stage1 LDSMs done (free for staging)

    // ---- epilogue phase A: bias + msg partials + STS-staged output tile ----
    float* xs = (float*)sm;                // [64][128] fp32 (over stage0)
    float* smsg = (float*)(sm + OFF_MSG);  // [2][64]
    const int il = wn >> 1;                // this warp's i within the pair
#pragma unroll
    for (int mf = 0; mf < 2; mf++) {
        int r0 = wm * 32 + mf * 16 + (l >> 2);
        float p0 = 0.0f, p1 = 0.0f;
#pragma unroll
        for (int nf = 0; nf < 8; nf++) {
            int cl = wn * 64 + nf * 8 + (l & 3) * 2;
            int col = colBase + cl;
            int jl = cl & 127;
            float b0 = bias[col], b1 = bias[col + 1];
            float t00 = acc[mf][nf][0] + b0, t01 = acc[mf][nf][1] + b1;
            float t10 = acc[mf][nf][2] + b0, t11 = acc[mf][nf][3] + b1;
            __half2 h0 = __floats2half2_rn(t00, t01);
            __half2 h1 = __floats2half2_rn(t10, t11);
            // swizzled staging: row stride 512B, XOR (row&7)<<4 keeps STS conflict-free
            uint32_t o0 = ((uint32_t)r0 << 9) + (((uint32_t)cl << 1) ^ ((r0 & 7) << 4));
            uint32_t o1 = ((uint32_t)(r0 + 8) << 9) + (((uint32_t)cl << 1) ^ (((r0 + 8) & 7) << 4));
            *(uint32_t*)(sm + STAGE + o0) = *(uint32_t*)&h0;
            *(uint32_t*)(sm + STAGE + o1) = *(uint32_t*)&h1;
            p0 += t00 * xs[r0 * 128 + jl] + t01 * xs[r0 * 128 + jl + 1];
            p1 += t10 * xs[(r0 + 8) * 128 + jl] + t11 * xs[(r0 + 8) * 128 + jl + 1];
        }
        p0 += __shfl_xor_sync(0xffffffffu, p0, 1);
        p0 += __shfl_xor_sync(0xffffffffu, p0, 2);
        p1 += __shfl_xor_sync(0xffffffffu, p1, 1);
        p1 += __shfl_xor_sync(0xffffffffu, p1, 2);
        if ((l & 3) == 0) {
            atomicAdd(&smsg[il * 64 + r0], p0);
            atomicAdd(&smsg[il * 64 + r0 + 8], p1);
        }
    }
    __syncthreads();

    // ---- epilogue phase B: dense 16B write-out of the staged tile ----
    {
        int row = wid * 8 + (l >> 2);                  // 8 warps x 8 rows
        char* gdst = (char*)&g_transform[(size_t)(rowBase + row) * 16384 + colBase];
#pragma unroll
        for (int s = 0; s < 8; s++) {
            uint32_t chunkByte = (uint32_t)((l & 3) * 16 + s * 64);
            uint32_t offb = ((uint32_t)row << 9) + (chunkByte ^ ((row & 7) << 4));
            uint4 vv = *(uint4*)(sm + STAGE + offb);
            __stcs((uint4*)(gdst + chunkByte), vv);
        }
    }
    if (tid < 128) {
        int r = tid & 63, ii = tid >> 6;
        int dst = node_out[rowBase + r];
        atomicAdd(&g_upd[(size_t)dst * 128 + 2 * blockIdx.x + ii], smsg[ii * 64 + r]);
    }
}

// ---------------- message (layers 2,3): warp-per-row matvec, fp16 transform --
__global__ void k_message(const int* __restrict__ node_in, const int* __restrict__ node_out) {
    int e = blockIdx.x, t = threadIdx.x;
    __shared__ float v[Hd];
    int src = node_in[e];
    v[t] = g_h[src * Hd + t];
    __syncthreads();
    int lane = t & 31, w = t >> 5;
    int dst = node_out[e];
    const __half* T = &g_transform[(size_t)e * 16384];
    float v0 = v[lane * 4 + 0], v1 = v[lane * 4 + 1], v2 = v[lane * 4 + 2], v3 = v[lane * 4 + 3];
#pragma unroll
    for (int r = w; r < Hd; r += 4) {
        uint2 raw = __ldcs((const uint2*)&T[r * 128 + lane * 4]);
        float2 a = __half22float2(*(__half2*)&raw.x);
        float2 b = __half22float2(*(__half2*)&raw.y);
        float s = a.x * v0 + a.y * v1 + b.x * v2 + b.y * v3;
#pragma unroll
        for (int o = 16; o; o >>= 1) s += __shfl_down_sync(0xffffffffu, s, o);
        if (lane == 0) atomicAdd(&g_upd[dst * Hd + r], s);
    }
}

// ---------------- GRU: 8 nodes per block (more warps/SM); re-zeroes g_upd ----
__global__ void __launch_bounds__(128) k_gru(const float* __restrict__ b_ih,
                                             const float* __restrict__ b_hh,
                                             float* __restrict__ out) {
    int n0 = blockIdx.x * 8;
    int t = threadIdx.x;
    __shared__ float xs[8][Hd];
    __shared__ float hs[8][Hd];
#pragma unroll
    for (int q = 0; q < 8; q++) {
        xs[q][t] = fmaxf(g_upd[(n0 + q) * Hd + t], 0.0f);
        g_upd[(n0 + q) * Hd + t] = 0.0f;
        hs[q][t] = g_h[(n0 + q) * Hd + t];
    }
    __syncthreads();
    float ir[8], iz[8], in_[8], hr[8], hz[8], hn[8];
    float bir = b_ih[t], biz = b_ih[128 + t], bin = b_ih[256 + t];
    float bhr = b_hh[t], bhz = b_hh[128 + t], bhn = b_hh[256 + t];
#pragma unroll
    for (int q = 0; q < 8; q++) { ir[q] = bir; iz[q] = biz; in_[q] = bin; hr[q] = bhr; hz[q] = bhz; hn[q] = bhn; }
    for (int j = 0; j < Hd; j++) {
        float wi0 = g_wihT[j * 384 + t], wi1 = g_wihT[j * 384 + 128 + t], wi2 = g_wihT[j * 384 + 256 + t];
        float wh0 = g_whhT[j * 384 + t], wh1 = g_whhT[j * 384 + 128 + t], wh2 = g_whhT[j * 384 + 256 + t];
#pragma unroll
        for (int q = 0; q < 8; q++) {
            float x = xs[q][j], h = hs[q][j];
            ir[q] += x * wi0; iz[q] += x * wi1; in_[q] += x * wi2;
            hr[q] += h * wh0; hz[q] += h * wh1; hn[q] += h * wh2;
        }
    }
#pragma unroll
    for (int q = 0; q < 8; q++) {
        float r = sigm(ir[q] + hr[q]);
        float z = sigm(iz[q] + hz[q]);
        float nn = tanhf(in_[q] + r * hn[q]);
        float hv = (1.0f - z) * nn + z * hs[q][t];
        g_h[(n0 + q) * Hd + t] = hv;
        if (out) out[(size_t)(n0 + q) * Hd + t] = hv;
    }
}

// ---------------- fused Set2Set step: LSTM + attend (4 graphs/block) ---------
__global__ void __launch_bounds__(128) k_s2s(const float* __restrict__ b_ih,
        const float* __restrict__ b_hh, const int* __restrict__ n2g,
        int last, float* __restrict__ out) {
    int g0 = blockIdx.x * 4;
    int t = threadIdx.x;
    int w = t >> 5, l = t & 31;
    __shared__ float qs[4][256];
    __shared__ float hsm[4][128];
    __shared__ int seg[5];
#pragma unroll
    for (int g = 0; g < 4; g++) {
        qs[g][t] = g_qs[(g0 + g) * 256 + t];
        qs[g][128 + t] = g_qs[(g0 + g) * 256 + 128 + t];
        hsm[g][t] = g_hs[(g0 + g) * Hd + t];
    }
    if (t < 5) {
        int target = g0 + t;
        int lo = 0, hi = Nn;
        while (lo < hi) { int m = (lo + hi) >> 1; if (n2g[m] < target) lo = m + 1; else hi = m; }
        seg[t] = lo;
    }
    __syncthreads();

    // ---- LSTM for 4 graphs ----
    float gi[4], gf[4], gg[4], go[4];
    {
        float bi = b_ih[t] + b_hh[t];
        float bf = b_ih[128 + t] + b_hh[128 + t];
        float bg = b_ih[256 + t] + b_hh[256 + t];
        float bo = b_ih[384 + t] + b_hh[384 + t];
#pragma unroll
        for (int g = 0; g < 4; g++) { gi[g] = bi; gf[g] = bf; gg[g] = bg; go[g] = bo; }
    }
    for (int j = 0; j < 256; j++) {
        const float* wi = &g_lihT[j * 512];
        float w0 = wi[t], w1 = wi[128 + t], w2 = wi[256 + t], w3 = wi[384 + t];
#pragma unroll
        for (int g = 0; g < 4; g++) {
            float q = qs[g][j];
            gi[g] += q * w0; gf[g] += q * w1; gg[g] += q * w2; go[g] += q * w3;
        }
    }
    for (int j = 0; j < Hd; j++) {
        const float* wh = &g_lhhT[j * 512];
        float w0 = wh[t], w1 = wh[128 + t], w2 = wh[256 + t], w3 = wh[384 + t];
#pragma unroll
        for (int g = 0; g < 4; g++) {
            float h = hsm[g][j];
            gi[g] += h * w0; gf[g] += h * w1; gg[g] += h * w2; go[g] += h * w3;
        }
    }
    __syncthreads();      // hsm reads done before overwrite
#pragma unroll
    for (int g = 0; g < 4; g++) {
        float c = sigm(gf[g]) * g_cs[(g0 + g) * Hd + t] + sigm(gi[g]) * tanhf(gg[g]);
        float h = sigm(go[g]) * tanhf(c);
        g_cs[(g0 + g) * Hd + t] = c;
        g_hs[(g0 + g) * Hd + t] = h;
        hsm[g][t] = h;
    }
    __syncthreads();

    // ---- attend: warp w handles graph g0+w (online segment softmax) ----
    {
        int b = g0 + w;
        int lo = seg[w], hi = seg[w + 1];
        float4 hv = *(float4*)&hsm[w][l * 4];
        float m = -INFINITY, s = 0.0f;
        float p0 = 0.0f, p1 = 0.0f, p2 = 0.0f, p3 = 0.0f;
        for (int i = lo; i < hi; i++) {
            float4 nf = *(const float4*)&g_h[(size_t)i * Hd + l * 4];
            float d = hv.x * nf.x + hv.y * nf.y + hv.z * nf.z + hv.w * nf.w;
#pragma unroll
            for (int o = 16; o; o >>= 1) d += __shfl_xor_sync(0xffffffffu, d, o);
            float mn = fmaxf(m, d);
            float corr = expf(m - mn);     // exp(-inf) = 0 first iter
            float wg = expf(d - mn);
            s = s * corr + wg;
            p0 = p0 * corr + wg * nf.x; p1 = p1 * corr + wg * nf.y;
            p2 = p2 * corr + wg * nf.z; p3 = p3 * corr + wg * nf.w;
            m = mn;
        }
        float inv = (s > 0.0f) ? 1.0f / s : 0.0f;
        float4 pooled = make_float4(p0 * inv, p1 * inv, p2 * inv, p3 * inv);
        *(float4*)&g_qs[b * 256 + l * 4] = hv;
        *(float4*)&g_qs[b * 256 + 128 + l * 4] = pooled;
        if (last) {
            *(float4*)&out[b * 256 + l * 4] = hv;
            *(float4*)&out[b * 256 + 128 + l * 4] = pooled;
        }
    }
}

extern "C" void kernel_launch(void* const* d_in, const int* in_sizes, int n_in,
                              void* d_out, int out_size) {
    const int*   unit_type    = (const int*)d_in[0];
    const int*   node_in      = (const int*)d_in[1];
    const int*   node_out     = (const int*)d_in[2];
    const int*   node2graph   = (const int*)d_in[3];
    const float* edge_feature = (const float*)d_in[4];
    const float* embedding    = (const float*)d_in[5];
    const float* mlp_w1       = (const float*)d_in[6];
    const float* mlp_b1       = (const float*)d_in[7];
    const float* mlp_w2       = (const float*)d_in[8];
    const float* mlp_b2       = (const float*)d_in[9];
    const float* gru_w_ih     = (const float*)d_in[10];
    const float* gru_w_hh     = (const float*)d_in[11];
    const float* gru_b_ih     = (const float*)d_in[12];
    const float* gru_b_hh     = (const float*)d_in[13];
    const float* lstm_w_ih    = (const float*)d_in[14];
    const float* lstm_w_hh    = (const float*)d_in[15];
    const float* lstm_b_ih    = (const float*)d_in[16];
    const float* lstm_b_hh    = (const float*)d_in[17];
    float* out = (float*)d_out;

    cudaFuncSetAttribute(k_gemm_mma, cudaFuncAttributeMaxDynamicSharedMemorySize, SMEM_GEMM);

    k_init_h<<<Nn, Hd>>>(unit_type, embedding);
    k_prep<<<8128, 256>>>(mlp_w2, gru_w_ih, gru_w_hh, lstm_w_ih, lstm_w_hh);
    k_edge_hidden<<<Ee, Hd>>>(edge_feature, mlp_w1, mlp_b1);
    // GEMM + fused layer-1 message (g_upd pre-zeroed by k_prep)
    k_gemm_mma<<<dim3(64, 256), 256, SMEM_GEMM>>>(mlp_b2, node_in, node_out);
    k_gru<<<Nn / 8, Hd>>>(gru_b_ih, gru_b_hh, nullptr);

    for (int l = 1; l < 3; l++) {
        k_message<<<Ee, Hd>>>(node_in, node_out);
        // last GRU writes node_feature directly into the output
        k_gru<<<Nn / 8, Hd>>>(gru_b_ih, gru_b_hh, (l == 2) ? out + Bg * 256 : nullptr);
    }

    for (int s = 0; s < 3; s++) {
        k_s2s<<<Bg / 4, 128>>>(lstm_b_ih, lstm_b_hh, node2graph, s == 2, out);
    }
}